// round 3
// baseline (speedup 1.0000x reference)
#include <cuda_runtime.h>

#define BB  32
#define SS  577
#define EE  1024
#define HH  16
#define DD  64
#define BSS (BB*SS)   // 18464

// Scratch (device globals: allocation-free per harness rules)
__device__ float g_Q[BB*HH*SS*DD];
__device__ float g_K[BB*HH*SS*DD];
__device__ float g_V[BB*HH*SS*DD];
__device__ float g_O[BSS*EE];

// ---------------------------------------------------------------------------
// QKV projection: out[b,h,s,d] = sum_e x[(b,s),e] * W[h,e,d]
// Tiled SGEMM: 128(M) x 128(N) x 8(K), 256 threads, 8x8 microtile.
// N dimension = h*64+d (1024 per weight matrix).
// ---------------------------------------------------------------------------
__global__ __launch_bounds__(256, 2)
void qkv_kernel(const float* __restrict__ x, const float* __restrict__ W,
                float* __restrict__ out)
{
    __shared__ float As[8][128];
    __shared__ float Bs[8][128];
    const int tid = threadIdx.x;
    const int tx = tid & 15, ty = tid >> 4;
    const int m0 = blockIdx.x * 128;
    const int n0 = blockIdx.y * 128;

    float acc[8][8];
    #pragma unroll
    for (int i = 0; i < 8; i++)
        #pragma unroll
        for (int j = 0; j < 8; j++) acc[i][j] = 0.f;

    // A loader: 128 rows x 8 k, one float4/thread
    const int a_row = tid >> 1;
    const int a_kq  = (tid & 1) * 4;
    const bool a_ok = (m0 + a_row) < BSS;
    const float* Ap = x + (size_t)(m0 + a_row) * EE + a_kq;

    // B loader: 8 k x 128 n, one float4/thread. W is [H][E][D]; n -> (h,d).
    const int b_k  = tid >> 5;
    const int b_nq = (tid & 31) * 4;
    const int n_g  = n0 + b_nq;
    const float* Wp = W + (size_t)(n_g >> 6) * (EE * DD) + (n_g & 63);

    for (int kt = 0; kt < EE; kt += 8) {
        float4 av = a_ok ? *(const float4*)(Ap + kt) : make_float4(0.f, 0.f, 0.f, 0.f);
        float4 bv = *(const float4*)(Wp + (size_t)(kt + b_k) * DD);
        __syncthreads();
        As[a_kq + 0][a_row] = av.x; As[a_kq + 1][a_row] = av.y;
        As[a_kq + 2][a_row] = av.z; As[a_kq + 3][a_row] = av.w;
        *(float4*)&Bs[b_k][b_nq] = bv;
        __syncthreads();
        #pragma unroll
        for (int k = 0; k < 8; k++) {
            float4 a0 = *(float4*)&As[k][ty * 4];
            float4 a1 = *(float4*)&As[k][64 + ty * 4];
            float4 b0 = *(float4*)&Bs[k][tx * 4];
            float4 b1 = *(float4*)&Bs[k][64 + tx * 4];
            float ar[8] = {a0.x, a0.y, a0.z, a0.w, a1.x, a1.y, a1.z, a1.w};
            float br[8] = {b0.x, b0.y, b0.z, b0.w, b1.x, b1.y, b1.z, b1.w};
            #pragma unroll
            for (int i = 0; i < 8; i++)
                #pragma unroll
                for (int j = 0; j < 8; j++)
                    acc[i][j] = fmaf(ar[i], br[j], acc[i][j]);
        }
    }

    #pragma unroll
    for (int i = 0; i < 8; i++) {
        int r = (i < 4) ? (ty * 4 + i) : (64 + ty * 4 + i - 4);
        int m = m0 + r;
        if (m >= BSS) continue;
        int bb = m / SS;
        int ss = m - bb * SS;
        #pragma unroll
        for (int j = 0; j < 8; j++) {
            int c = (j < 4) ? (tx * 4 + j) : (64 + tx * 4 + j - 4);
            int n = n0 + c;
            out[(((size_t)bb * HH + (n >> 6)) * SS + ss) * DD + (n & 63)] = acc[i][j];
        }
    }
}

// ---------------------------------------------------------------------------
// Flash attention per (b, h): 64-query tile/block, 64-key tiles, online
// softmax. Thread (tx,ty): score rows ty*4+i, cols tx+16*j (strided cols so
// smem reads are broadcast / <=2-way with stride 68).
// ---------------------------------------------------------------------------
#define TSTR 68
#define ATTN_SMEM (4 * 64 * TSTR * sizeof(float))

__global__ __launch_bounds__(256, 2)
void attn_kernel()
{
    extern __shared__ float sm[];
    float* Qs = sm;
    float* Ks = sm + 64 * TSTR;
    float* Vs = sm + 2 * 64 * TSTR;
    float* Ps = sm + 3 * 64 * TSTR;

    const int tid = threadIdx.x;
    const int tx = tid & 15, ty = tid >> 4;
    const int b = blockIdx.z, h = blockIdx.y;
    const int q0 = blockIdx.x * 64;

    const float* Qg = g_Q + (size_t)(b * HH + h) * SS * DD;
    const float* Kg = g_K + (size_t)(b * HH + h) * SS * DD;
    const float* Vg = g_V + (size_t)(b * HH + h) * SS * DD;

    const int lrow = tid >> 4;        // 0..15
    const int ldq  = (tid & 15) * 4;  // 0..60

    #pragma unroll
    for (int it = 0; it < 4; it++) {
        int row = it * 16 + lrow;
        int q = q0 + row;
        float4 v = (q < SS) ? *(const float4*)(Qg + (size_t)q * DD + ldq)
                            : make_float4(0.f, 0.f, 0.f, 0.f);
        *(float4*)&Qs[row * TSTR + ldq] = v;
    }

    float m_[4], l_[4], o_[4][4];
    #pragma unroll
    for (int i = 0; i < 4; i++) {
        m_[i] = -1e30f; l_[i] = 0.f;
        #pragma unroll
        for (int j = 0; j < 4; j++) o_[i][j] = 0.f;
    }

    const int nKT = (SS + 63) / 64;   // 10
    for (int jt = 0; jt < nKT; jt++) {
        int j0 = jt * 64;
        __syncthreads();   // prev iter's Ks/Vs/Ps fully consumed
        #pragma unroll
        for (int it = 0; it < 4; it++) {
            int row = it * 16 + lrow;
            int t = j0 + row;
            float4 kv, vv;
            if (t < SS) {
                kv = *(const float4*)(Kg + (size_t)t * DD + ldq);
                vv = *(const float4*)(Vg + (size_t)t * DD + ldq);
            } else {
                kv = make_float4(0.f, 0.f, 0.f, 0.f);
                vv = kv;
            }
            *(float4*)&Ks[row * TSTR + ldq] = kv;
            *(float4*)&Vs[row * TSTR + ldq] = vv;
        }
        __syncthreads();

        // S = Q @ K^T
        float s_[4][4];
        #pragma unroll
        for (int i = 0; i < 4; i++)
            #pragma unroll
            for (int j = 0; j < 4; j++) s_[i][j] = 0.f;

        #pragma unroll 8
        for (int d = 0; d < 64; d++) {
            float a0 = Qs[(ty * 4 + 0) * TSTR + d];
            float a1 = Qs[(ty * 4 + 1) * TSTR + d];
            float a2 = Qs[(ty * 4 + 2) * TSTR + d];
            float a3 = Qs[(ty * 4 + 3) * TSTR + d];
            float c0 = Ks[(tx +  0) * TSTR + d];
            float c1 = Ks[(tx + 16) * TSTR + d];
            float c2 = Ks[(tx + 32) * TSTR + d];
            float c3 = Ks[(tx + 48) * TSTR + d];
            s_[0][0] = fmaf(a0, c0, s_[0][0]); s_[0][1] = fmaf(a0, c1, s_[0][1]);
            s_[0][2] = fmaf(a0, c2, s_[0][2]); s_[0][3] = fmaf(a0, c3, s_[0][3]);
            s_[1][0] = fmaf(a1, c0, s_[1][0]); s_[1][1] = fmaf(a1, c1, s_[1][1]);
            s_[1][2] = fmaf(a1, c2, s_[1][2]); s_[1][3] = fmaf(a1, c3, s_[1][3]);
            s_[2][0] = fmaf(a2, c0, s_[2][0]); s_[2][1] = fmaf(a2, c1, s_[2][1]);
            s_[2][2] = fmaf(a2, c2, s_[2][2]); s_[2][3] = fmaf(a2, c3, s_[2][3]);
            s_[3][0] = fmaf(a3, c0, s_[3][0]); s_[3][1] = fmaf(a3, c1, s_[3][1]);
            s_[3][2] = fmaf(a3, c2, s_[3][2]); s_[3][3] = fmaf(a3, c3, s_[3][3]);
        }

        // scale + key-boundary mask
        #pragma unroll
        for (int j = 0; j < 4; j++) {
            bool valid = (j0 + tx + 16 * j) < SS;
            #pragma unroll
            for (int i = 0; i < 4; i++)
                s_[i][j] = valid ? s_[i][j] * 0.125f : -1e30f;
        }

        // online softmax (row groups = 16 consecutive lanes)
        #pragma unroll
        for (int i = 0; i < 4; i++) {
            float mx = fmaxf(fmaxf(s_[i][0], s_[i][1]), fmaxf(s_[i][2], s_[i][3]));
            #pragma unroll
            for (int off = 8; off >= 1; off >>= 1)
                mx = fmaxf(mx, __shfl_xor_sync(0xffffffffu, mx, off));
            float mn = fmaxf(m_[i], mx);
            float corr = __expf(m_[i] - mn);
            m_[i] = mn;
            float rs = 0.f;
            #pragma unroll
            for (int j = 0; j < 4; j++) { s_[i][j] = __expf(s_[i][j] - mn); rs += s_[i][j]; }
            #pragma unroll
            for (int off = 8; off >= 1; off >>= 1)
                rs += __shfl_xor_sync(0xffffffffu, rs, off);
            l_[i] = l_[i] * corr + rs;
            #pragma unroll
            for (int j = 0; j < 4; j++) o_[i][j] *= corr;
        }

        // P to smem
        #pragma unroll
        for (int i = 0; i < 4; i++)
            #pragma unroll
            for (int j = 0; j < 4; j++)
                Ps[(ty * 4 + i) * TSTR + tx + 16 * j] = s_[i][j];
        __syncthreads();

        // O += P @ V  (O cols d = tx + 16*j)
        #pragma unroll 8
        for (int t = 0; t < 64; t++) {
            float a0 = Ps[(ty * 4 + 0) * TSTR + t];
            float a1 = Ps[(ty * 4 + 1) * TSTR + t];
            float a2 = Ps[(ty * 4 + 2) * TSTR + t];
            float a3 = Ps[(ty * 4 + 3) * TSTR + t];
            float v0 = Vs[t * TSTR + tx];
            float v1 = Vs[t * TSTR + tx + 16];
            float v2 = Vs[t * TSTR + tx + 32];
            float v3 = Vs[t * TSTR + tx + 48];
            o_[0][0] = fmaf(a0, v0, o_[0][0]); o_[0][1] = fmaf(a0, v1, o_[0][1]);
            o_[0][2] = fmaf(a0, v2, o_[0][2]); o_[0][3] = fmaf(a0, v3, o_[0][3]);
            o_[1][0] = fmaf(a1, v0, o_[1][0]); o_[1][1] = fmaf(a1, v1, o_[1][1]);
            o_[1][2] = fmaf(a1, v2, o_[1][2]); o_[1][3] = fmaf(a1, v3, o_[1][3]);
            o_[2][0] = fmaf(a2, v0, o_[2][0]); o_[2][1] = fmaf(a2, v1, o_[2][1]);
            o_[2][2] = fmaf(a2, v2, o_[2][2]); o_[2][3] = fmaf(a2, v3, o_[2][3]);
            o_[3][0] = fmaf(a3, v0, o_[3][0]); o_[3][1] = fmaf(a3, v1, o_[3][1]);
            o_[3][2] = fmaf(a3, v2, o_[3][2]); o_[3][3] = fmaf(a3, v3, o_[3][3]);
        }
    }

    // normalize + store concat-head layout [b, s, h*D + d]
    #pragma unroll
    for (int i = 0; i < 4; i++) {
        int q = q0 + ty * 4 + i;
        if (q >= SS) continue;
        float inv = 1.0f / l_[i];
        size_t base = ((size_t)b * SS + q) * EE + h * DD;
        #pragma unroll
        for (int j = 0; j < 4; j++)
            g_O[base + tx + 16 * j] = o_[i][j] * inv;
    }
}

// ---------------------------------------------------------------------------
// Output projection: out[m, n] = sum_k O[m, k] * Wo[n, k] + bo[n]
// Same SGEMM skeleton, B loaded transposed from Wo rows.
// ---------------------------------------------------------------------------
__global__ __launch_bounds__(256, 2)
void proj_kernel(const float* __restrict__ A, const float* __restrict__ Wo,
                 const float* __restrict__ bo, float* __restrict__ out)
{
    __shared__ float As[8][128];
    __shared__ float Bs[8][128];
    const int tid = threadIdx.x;
    const int tx = tid & 15, ty = tid >> 4;
    const int m0 = blockIdx.x * 128;
    const int n0 = blockIdx.y * 128;

    float acc[8][8];
    #pragma unroll
    for (int i = 0; i < 8; i++)
        #pragma unroll
        for (int j = 0; j < 8; j++) acc[i][j] = 0.f;

    const int a_row = tid >> 1;
    const int a_kq  = (tid & 1) * 4;
    const bool a_ok = (m0 + a_row) < BSS;
    const float* Ap = A + (size_t)(m0 + a_row) * EE + a_kq;

    const int b_n  = tid >> 1;          // 0..127
    const int b_kq = (tid & 1) * 4;
    const float* Wp = Wo + (size_t)(n0 + b_n) * EE + b_kq;

    for (int kt = 0; kt < EE; kt += 8) {
        float4 av = a_ok ? *(const float4*)(Ap + kt) : make_float4(0.f, 0.f, 0.f, 0.f);
        float4 bv = *(const float4*)(Wp + kt);
        __syncthreads();
        As[a_kq + 0][a_row] = av.x; As[a_kq + 1][a_row] = av.y;
        As[a_kq + 2][a_row] = av.z; As[a_kq + 3][a_row] = av.w;
        Bs[b_kq + 0][b_n] = bv.x; Bs[b_kq + 1][b_n] = bv.y;
        Bs[b_kq + 2][b_n] = bv.z; Bs[b_kq + 3][b_n] = bv.w;
        __syncthreads();
        #pragma unroll
        for (int k = 0; k < 8; k++) {
            float4 a0 = *(float4*)&As[k][ty * 4];
            float4 a1 = *(float4*)&As[k][64 + ty * 4];
            float4 b0 = *(float4*)&Bs[k][tx * 4];
            float4 b1 = *(float4*)&Bs[k][64 + tx * 4];
            float ar[8] = {a0.x, a0.y, a0.z, a0.w, a1.x, a1.y, a1.z, a1.w};
            float br[8] = {b0.x, b0.y, b0.z, b0.w, b1.x, b1.y, b1.z, b1.w};
            #pragma unroll
            for (int i = 0; i < 8; i++)
                #pragma unroll
                for (int j = 0; j < 8; j++)
                    acc[i][j] = fmaf(ar[i], br[j], acc[i][j]);
        }
    }

    #pragma unroll
    for (int i = 0; i < 8; i++) {
        int r = (i < 4) ? (ty * 4 + i) : (64 + ty * 4 + i - 4);
        int m = m0 + r;
        if (m >= BSS) continue;
        #pragma unroll
        for (int j = 0; j < 8; j++) {
            int c = (j < 4) ? (tx * 4 + j) : (64 + tx * 4 + j - 4);
            int n = n0 + c;
            out[(size_t)m * EE + n] = acc[i][j] + __ldg(&bo[n]);
        }
    }
}

// ---------------------------------------------------------------------------
extern "C" void kernel_launch(void* const* d_in, const int* in_sizes, int n_in,
                              void* d_out, int out_size)
{
    (void)in_sizes; (void)n_in; (void)out_size;
    const float* x  = (const float*)d_in[0];
    const float* Wq = (const float*)d_in[1];
    const float* Wk = (const float*)d_in[2];
    const float* Wv = (const float*)d_in[3];
    const float* Wo = (const float*)d_in[4];
    const float* bo = (const float*)d_in[5];
    float* out = (float*)d_out;

    float *pQ, *pK, *pV, *pO;
    cudaGetSymbolAddress((void**)&pQ, g_Q);
    cudaGetSymbolAddress((void**)&pK, g_K);
    cudaGetSymbolAddress((void**)&pV, g_V);
    cudaGetSymbolAddress((void**)&pO, g_O);

    cudaFuncSetAttribute(attn_kernel,
                         cudaFuncAttributeMaxDynamicSharedMemorySize,
                         (int)ATTN_SMEM);

    dim3 gGemm((BSS + 127) / 128, EE / 128);   // (145, 8)
    qkv_kernel<<<gGemm, 256>>>(x, Wq, pQ);
    qkv_kernel<<<gGemm, 256>>>(x, Wk, pK);
    qkv_kernel<<<gGemm, 256>>>(x, Wv, pV);

    dim3 gAttn((SS + 63) / 64, HH, BB);        // (10, 16, 32)
    attn_kernel<<<gAttn, 256, ATTN_SMEM>>>();

    proj_kernel<<<gGemm, 256>>>(pO, Wo, bo, out);
}

// round 6
// speedup vs baseline: 1.8439x; 1.8439x over previous
#include <cuda_runtime.h>
#include <cuda_bf16.h>
#include <cstdint>

#define BB  32
#define SS  577
#define EE  1024
#define HH  16
#define DD  64
#define BSS (BB*SS)     // 18464
#define MPAD 18560      // 145*128
#define NQKV 3072

// ---------------------------------------------------------------------------
// Device global scratch (allocation-free per harness rules)
// ---------------------------------------------------------------------------
__device__ float g_Q[(size_t)BB*HH*SS*DD];
__device__ float g_K[(size_t)BB*HH*SS*DD];
__device__ float g_V[(size_t)BB*HH*SS*DD];
__device__ float g_O[(size_t)BSS*EE];

__device__ __nv_bfloat16 g_Xh[(size_t)MPAD*EE];
__device__ __nv_bfloat16 g_Xl[(size_t)MPAD*EE];
__device__ __nv_bfloat16 g_Wh[(size_t)NQKV*EE];
__device__ __nv_bfloat16 g_Wl[(size_t)NQKV*EE];
__device__ __nv_bfloat16 g_Uh[(size_t)EE*EE];
__device__ __nv_bfloat16 g_Ul[(size_t)EE*EE];
__device__ __nv_bfloat16 g_Oh[(size_t)MPAD*EE];
__device__ __nv_bfloat16 g_Ol[(size_t)MPAD*EE];

// ---------------------------------------------------------------------------
// Helpers (sm_80-baseline PTX only — NO tcgen05, harness compiles compute_103)
// ---------------------------------------------------------------------------
__device__ __forceinline__ uint32_t smem_u32(const void* p) {
    uint32_t a;
    asm("{ .reg .u64 t; cvta.to.shared.u64 t, %1; cvt.u32.u64 %0, t; }"
        : "=r"(a) : "l"(p));
    return a;
}

__device__ __forceinline__ uint32_t swz(uint32_t off) {   // SW128 XOR swizzle
    return off ^ ((off >> 3) & 0x70);
}

#define CP16(dst, src) \
    asm volatile("cp.async.cg.shared.global [%0], [%1], 16;" \
                 :: "r"(dst), "l"(src) : "memory")

#define LDSM4(r0, r1, r2, r3, addr) \
    asm volatile("ldmatrix.sync.aligned.m8n8.x4.shared.b16 {%0,%1,%2,%3}, [%4];" \
                 : "=r"(r0), "=r"(r1), "=r"(r2), "=r"(r3) : "r"(addr))

#define MMA16816(d, a, b) \
    asm volatile("mma.sync.aligned.m16n8k16.row.col.f32.bf16.bf16.f32 " \
                 "{%0,%1,%2,%3}, {%4,%5,%6,%7}, {%8,%9}, {%0,%1,%2,%3};" \
                 : "+f"((d)[0]), "+f"((d)[1]), "+f"((d)[2]), "+f"((d)[3]) \
                 : "r"((a)[0]), "r"((a)[1]), "r"((a)[2]), "r"((a)[3]), \
                   "r"((b)[0]), "r"((b)[1]))

// ---------------------------------------------------------------------------
// fp32 -> bf16 hi/lo split (zero pad beyond n_valid)
// ---------------------------------------------------------------------------
__global__ void split_kernel(const float* __restrict__ src,
                             __nv_bfloat16* __restrict__ hd,
                             __nv_bfloat16* __restrict__ ld,
                             size_t n_valid, size_t n_total)
{
    size_t i = ((size_t)blockIdx.x * 256 + threadIdx.x) * 4;
    if (i >= n_total) return;
    float4 v = make_float4(0.f, 0.f, 0.f, 0.f);
    if (i < n_valid) v = *(const float4*)(src + i);
    __nv_bfloat16 h0 = __float2bfloat16_rn(v.x);
    __nv_bfloat16 h1 = __float2bfloat16_rn(v.y);
    __nv_bfloat16 h2 = __float2bfloat16_rn(v.z);
    __nv_bfloat16 h3 = __float2bfloat16_rn(v.w);
    __nv_bfloat16 l0 = __float2bfloat16_rn(v.x - __bfloat162float(h0));
    __nv_bfloat16 l1 = __float2bfloat16_rn(v.y - __bfloat162float(h1));
    __nv_bfloat16 l2 = __float2bfloat16_rn(v.z - __bfloat162float(h2));
    __nv_bfloat16 l3 = __float2bfloat16_rn(v.w - __bfloat162float(h3));
    ((__nv_bfloat162*)hd)[(i >> 1) + 0] = __halves2bfloat162(h0, h1);
    ((__nv_bfloat162*)hd)[(i >> 1) + 1] = __halves2bfloat162(h2, h3);
    ((__nv_bfloat162*)ld)[(i >> 1) + 0] = __halves2bfloat162(l0, l1);
    ((__nv_bfloat162*)ld)[(i >> 1) + 1] = __halves2bfloat162(l2, l3);
}

// QKV weights [H][E][D] x3 -> B rows n = mat*1024 + h*64 + d, cols k = e
__global__ void convw_kernel(const float* __restrict__ Wq,
                             const float* __restrict__ Wk,
                             const float* __restrict__ Wv)
{
    int n = blockIdx.x;
    const float* W = (n < 1024) ? Wq : (n < 2048) ? Wk : Wv;
    int h = (n >> 6) & 15, d = n & 63;
    for (int k = threadIdx.x; k < EE; k += 256) {
        float v = W[((size_t)h * EE + k) * DD + d];
        __nv_bfloat16 hi = __float2bfloat16_rn(v);
        __nv_bfloat16 lo = __float2bfloat16_rn(v - __bfloat162float(hi));
        g_Wh[(size_t)n * EE + k] = hi;
        g_Wl[(size_t)n * EE + k] = lo;
    }
}

// ---------------------------------------------------------------------------
// Split-bf16 HMMA GEMM:  C[M,N] = A[M,K] * B[N,K]^T  (~fp32 accuracy)
//   128x128 block, 8 warps (warp = 32m x 64n), KC=64, cp.async double buffer.
//   mode 0: scatter to g_Q/g_K/g_V [b,h,s,d];  mode 1: outp = C + bias
// ---------------------------------------------------------------------------
#define TM 128
#define TN 128
#define KC 64
#define TILEB 16384                    // one 128x64 bf16 tile, 128B rows
#define STAGEB (4*TILEB)               // Ah, Al, Bh, Bl
#define GSMEM (2*STAGEB)               // 131072

__device__ __forceinline__ void issue_stage(
    uint32_t sbase,
    const __nv_bfloat16* __restrict__ Ah_, const __nv_bfloat16* __restrict__ Al_,
    const __nv_bfloat16* __restrict__ Bh_, const __nv_bfloat16* __restrict__ Bl_,
    int m0, int n0, int kt, int tid)
{
    #pragma unroll
    for (int i = 0; i < 4; i++) {
        int ff = tid + 256 * i;
        int row = ff >> 3, c = ff & 7;
        uint32_t doff = swz((uint32_t)(row * 128 + c * 16));
        size_t aoff = (size_t)(m0 + row) * EE + kt * KC + c * 8;
        size_t boff = (size_t)(n0 + row) * EE + kt * KC + c * 8;
        CP16(sbase + doff,              (const char*)(Ah_ + aoff));
        CP16(sbase + TILEB + doff,      (const char*)(Al_ + aoff));
        CP16(sbase + 2 * TILEB + doff,  (const char*)(Bh_ + boff));
        CP16(sbase + 3 * TILEB + doff,  (const char*)(Bl_ + boff));
    }
}

__device__ __forceinline__ void compute_chunk(
    uint32_t sbase, int wm, int wn, int lane, float (&acc)[2][8][4])
{
    const uint32_t aH = sbase, aL = sbase + TILEB;
    const uint32_t bH = sbase + 2 * TILEB, bL = sbase + 3 * TILEB;
    #pragma unroll
    for (int ks = 0; ks < 4; ks++) {
        uint32_t ah[2][4], al[2][4], bh[8][2], bl[8][2];
        #pragma unroll
        for (int mt = 0; mt < 2; mt++) {
            uint32_t off = swz((uint32_t)((wm + mt * 16 + (lane & 15)) * 128
                                        + (ks * 16 + (lane >> 4) * 8) * 2));
            LDSM4(ah[mt][0], ah[mt][1], ah[mt][2], ah[mt][3], aH + off);
            LDSM4(al[mt][0], al[mt][1], al[mt][2], al[mt][3], aL + off);
        }
        #pragma unroll
        for (int p = 0; p < 4; p++) {
            uint32_t off = swz((uint32_t)((wn + p * 16 + (lane & 7) + ((lane >> 4) & 1) * 8) * 128
                                        + (ks * 16 + ((lane >> 3) & 1) * 8) * 2));
            LDSM4(bh[2*p][0], bh[2*p][1], bh[2*p+1][0], bh[2*p+1][1], bH + off);
            LDSM4(bl[2*p][0], bl[2*p][1], bl[2*p+1][0], bl[2*p+1][1], bL + off);
        }
        #pragma unroll
        for (int mt = 0; mt < 2; mt++)
            #pragma unroll
            for (int nt = 0; nt < 8; nt++) {
                MMA16816(acc[mt][nt], ah[mt], bh[nt]);
                MMA16816(acc[mt][nt], al[mt], bh[nt]);
                MMA16816(acc[mt][nt], ah[mt], bl[nt]);
            }
    }
}

__global__ __launch_bounds__(256, 1)
void gemm_hmma(const __nv_bfloat16* __restrict__ Ah, const __nv_bfloat16* __restrict__ Al,
               const __nv_bfloat16* __restrict__ Bh, const __nv_bfloat16* __restrict__ Bl,
               float* __restrict__ outp, const float* __restrict__ bias, int mode)
{
    extern __shared__ __align__(1024) char smem[];
    const uint32_t sb = smem_u32(smem);
    const int tid = threadIdx.x, lane = tid & 31, wid = tid >> 5;
    const int m0 = blockIdx.x * TM, n0 = blockIdx.y * TN;
    const int wm = (wid & 3) * 32, wn = (wid >> 2) * 64;

    float acc[2][8][4];
    #pragma unroll
    for (int mt = 0; mt < 2; mt++)
        #pragma unroll
        for (int nt = 0; nt < 8; nt++)
            #pragma unroll
            for (int r = 0; r < 4; r++) acc[mt][nt][r] = 0.f;

    const int NK = EE / KC;   // 16
    issue_stage(sb, Ah, Al, Bh, Bl, m0, n0, 0, tid);
    asm volatile("cp.async.commit_group;" ::: "memory");

    int buf = 0;
    for (int kt = 0; kt < NK; kt++) {
        if (kt + 1 < NK) {
            issue_stage(sb + (buf ^ 1) * STAGEB, Ah, Al, Bh, Bl, m0, n0, kt + 1, tid);
            asm volatile("cp.async.commit_group;" ::: "memory");
            asm volatile("cp.async.wait_group 1;" ::: "memory");
        } else {
            asm volatile("cp.async.wait_group 0;" ::: "memory");
        }
        __syncthreads();
        compute_chunk(sb + buf * STAGEB, wm, wn, lane, acc);
        __syncthreads();
        buf ^= 1;
    }

    // Epilogue straight from registers
    #pragma unroll
    for (int mt = 0; mt < 2; mt++) {
        #pragma unroll
        for (int half = 0; half < 2; half++) {
            int m = m0 + wm + mt * 16 + (lane >> 2) + half * 8;
            if (m >= BSS) continue;
            if (mode == 0) {
                int bb = m / SS, ss = m - bb * SS;
                #pragma unroll
                for (int nt = 0; nt < 8; nt++) {
                    int col = n0 + wn + nt * 8 + (lane & 3) * 2;
                    int mat = col >> 10, h = (col >> 6) & 15, d = col & 63;
                    float* bp = (mat == 0 ? g_Q : (mat == 1 ? g_K : g_V))
                              + (((size_t)bb * HH + h) * SS + ss) * DD + d;
                    bp[0] = acc[mt][nt][half * 2 + 0];
                    bp[1] = acc[mt][nt][half * 2 + 1];
                }
            } else {
                float* op = outp + (size_t)m * EE;
                #pragma unroll
                for (int nt = 0; nt < 8; nt++) {
                    int col = n0 + wn + nt * 8 + (lane & 3) * 2;
                    op[col]     = acc[mt][nt][half * 2 + 0] + __ldg(bias + col);
                    op[col + 1] = acc[mt][nt][half * 2 + 1] + __ldg(bias + col + 1);
                }
            }
        }
    }
}

// ---------------------------------------------------------------------------
// Flash attention (unchanged from the R3-passing version)
// ---------------------------------------------------------------------------
#define TSTR 68
#define ATTN_SMEM (4 * 64 * TSTR * sizeof(float))

__global__ __launch_bounds__(256, 2)
void attn_kernel()
{
    extern __shared__ float sm[];
    float* Qs = sm;
    float* Ks = sm + 64 * TSTR;
    float* Vs = sm + 2 * 64 * TSTR;
    float* Ps = sm + 3 * 64 * TSTR;

    const int tid = threadIdx.x;
    const int tx = tid & 15, ty = tid >> 4;
    const int b = blockIdx.z, h = blockIdx.y;
    const int q0 = blockIdx.x * 64;

    const float* Qg = g_Q + (size_t)(b * HH + h) * SS * DD;
    const float* Kg = g_K + (size_t)(b * HH + h) * SS * DD;
    const float* Vg = g_V + (size_t)(b * HH + h) * SS * DD;

    const int lrow = tid >> 4;
    const int ldq  = (tid & 15) * 4;

    #pragma unroll
    for (int it = 0; it < 4; it++) {
        int row = it * 16 + lrow;
        int q = q0 + row;
        float4 v = (q < SS) ? *(const float4*)(Qg + (size_t)q * DD + ldq)
                            : make_float4(0.f, 0.f, 0.f, 0.f);
        *(float4*)&Qs[row * TSTR + ldq] = v;
    }

    float m_[4], l_[4], o_[4][4];
    #pragma unroll
    for (int i = 0; i < 4; i++) {
        m_[i] = -1e30f; l_[i] = 0.f;
        #pragma unroll
        for (int j = 0; j < 4; j++) o_[i][j] = 0.f;
    }

    const int nKT = (SS + 63) / 64;
    for (int jt = 0; jt < nKT; jt++) {
        int j0 = jt * 64;
        __syncthreads();
        #pragma unroll
        for (int it = 0; it < 4; it++) {
            int row = it * 16 + lrow;
            int t = j0 + row;
            float4 kv, vv;
            if (t < SS) {
                kv = *(const float4*)(Kg + (size_t)t * DD + ldq);
                vv = *(const float4*)(Vg + (size_t)t * DD + ldq);
            } else {
                kv = make_float4(0.f, 0.f, 0.f, 0.f);
                vv = kv;
            }
            *(float4*)&Ks[row * TSTR + ldq] = kv;
            *(float4*)&Vs[row * TSTR + ldq] = vv;
        }
        __syncthreads();

        float s_[4][4];
        #pragma unroll
        for (int i = 0; i < 4; i++)
            #pragma unroll
            for (int j = 0; j < 4; j++) s_[i][j] = 0.f;

        #pragma unroll 8
        for (int d = 0; d < 64; d++) {
            float a0 = Qs[(ty * 4 + 0) * TSTR + d];
            float a1 = Qs[(ty * 4 + 1) * TSTR + d];
            float a2 = Qs[(ty * 4 + 2) * TSTR + d];
            float a3 = Qs[(ty * 4 + 3) * TSTR + d];
            float c0 = Ks[(tx +  0) * TSTR + d];
            float c1 = Ks[(tx + 16) * TSTR + d];
            float c2 = Ks[(tx + 32) * TSTR + d];
            float c3 = Ks[(tx + 48) * TSTR + d];
            s_[0][0] = fmaf(a0, c0, s_[0][0]); s_[0][1] = fmaf(a0, c1, s_[0][1]);
            s_[0][2] = fmaf(a0, c2, s_[0][2]); s_[0][3] = fmaf(a0, c3, s_[0][3]);
            s_[1][0] = fmaf(a1, c0, s_[1][0]); s_[1][1] = fmaf(a1, c1, s_[1][1]);
            s_[1][2] = fmaf(a1, c2, s_[1][2]); s_[1][3] = fmaf(a1, c3, s_[1][3]);
            s_[2][0] = fmaf(a2, c0, s_[2][0]); s_[2][1] = fmaf(a2, c1, s_[2][1]);
            s_[2][2] = fmaf(a2, c2, s_[2][2]); s_[2][3] = fmaf(a2, c3, s_[2][3]);
            s_[3][0] = fmaf(a3, c0, s_[3][0]); s_[3][1] = fmaf(a3, c1, s_[3][1]);
            s_[3][2] = fmaf(a3, c2, s_[3][2]); s_[3][3] = fmaf(a3, c3, s_[3][3]);
        }

        #pragma unroll
        for (int j = 0; j < 4; j++) {
            bool valid = (j0 + tx + 16 * j) < SS;
            #pragma unroll
            for (int i = 0; i < 4; i++)
                s_[i][j] = valid ? s_[i][j] * 0.125f : -1e30f;
        }

        #pragma unroll
        for (int i = 0; i < 4; i++) {
            float mx = fmaxf(fmaxf(s_[i][0], s_[i][1]), fmaxf(s_[i][2], s_[i][3]));
            #pragma unroll
            for (int off = 8; off >= 1; off >>= 1)
                mx = fmaxf(mx, __shfl_xor_sync(0xffffffffu, mx, off));
            float mn = fmaxf(m_[i], mx);
            float corr = __expf(m_[i] - mn);
            m_[i] = mn;
            float rs = 0.f;
            #pragma unroll
            for (int j = 0; j < 4; j++) { s_[i][j] = __expf(s_[i][j] - mn); rs += s_[i][j]; }
            #pragma unroll
            for (int off = 8; off >= 1; off >>= 1)
                rs += __shfl_xor_sync(0xffffffffu, rs, off);
            l_[i] = l_[i] * corr + rs;
            #pragma unroll
            for (int j = 0; j < 4; j++) o_[i][j] *= corr;
        }

        #pragma unroll
        for (int i = 0; i < 4; i++)
            #pragma unroll
            for (int j = 0; j < 4; j++)
                Ps[(ty * 4 + i) * TSTR + tx + 16 * j] = s_[i][j];
        __syncthreads();

        #pragma unroll 8
        for (int t = 0; t < 64; t++) {
            float a0 = Ps[(ty * 4 + 0) * TSTR + t];
            float a1 = Ps[(ty * 4 + 1) * TSTR + t];
            float a2 = Ps[(ty * 4 + 2) * TSTR + t];
            float a3 = Ps[(ty * 4 + 3) * TSTR + t];
            float v0 = Vs[t * TSTR + tx];
            float v1 = Vs[t * TSTR + tx + 16];
            float v2 = Vs[t * TSTR + tx + 32];
            float v3 = Vs[t * TSTR + tx + 48];
            o_[0][0] = fmaf(a0, v0, o_[0][0]); o_[0][1] = fmaf(a0, v1, o_[0][1]);
            o_[0][2] = fmaf(a0, v2, o_[0][2]); o_[0][3] = fmaf(a0, v3, o_[0][3]);
            o_[1][0] = fmaf(a1, v0, o_[1][0]); o_[1][1] = fmaf(a1, v1, o_[1][1]);
            o_[1][2] = fmaf(a1, v2, o_[1][2]); o_[1][3] = fmaf(a1, v3, o_[1][3]);
            o_[2][0] = fmaf(a2, v0, o_[2][0]); o_[2][1] = fmaf(a2, v1, o_[2][1]);
            o_[2][2] = fmaf(a2, v2, o_[2][2]); o_[2][3] = fmaf(a2, v3, o_[2][3]);
            o_[3][0] = fmaf(a3, v0, o_[3][0]); o_[3][1] = fmaf(a3, v1, o_[3][1]);
            o_[3][2] = fmaf(a3, v2, o_[3][2]); o_[3][3] = fmaf(a3, v3, o_[3][3]);
        }
    }

    #pragma unroll
    for (int i = 0; i < 4; i++) {
        int q = q0 + ty * 4 + i;
        if (q >= SS) continue;
        float inv = 1.0f / l_[i];
        size_t base = ((size_t)b * SS + q) * EE + h * DD;
        #pragma unroll
        for (int j = 0; j < 4; j++)
            g_O[base + tx + 16 * j] = o_[i][j] * inv;
    }
}

// ---------------------------------------------------------------------------
extern "C" void kernel_launch(void* const* d_in, const int* in_sizes, int n_in,
                              void* d_out, int out_size)
{
    (void)in_sizes; (void)n_in; (void)out_size;
    const float* x  = (const float*)d_in[0];
    const float* Wq = (const float*)d_in[1];
    const float* Wk = (const float*)d_in[2];
    const float* Wv = (const float*)d_in[3];
    const float* Wo = (const float*)d_in[4];
    const float* bo = (const float*)d_in[5];
    float* out = (float*)d_out;

    __nv_bfloat16 *pXh, *pXl, *pWh, *pWl, *pUh, *pUl, *pOh, *pOl;
    float* pO;
    cudaGetSymbolAddress((void**)&pXh, g_Xh);
    cudaGetSymbolAddress((void**)&pXl, g_Xl);
    cudaGetSymbolAddress((void**)&pWh, g_Wh);
    cudaGetSymbolAddress((void**)&pWl, g_Wl);
    cudaGetSymbolAddress((void**)&pUh, g_Uh);
    cudaGetSymbolAddress((void**)&pUl, g_Ul);
    cudaGetSymbolAddress((void**)&pOh, g_Oh);
    cudaGetSymbolAddress((void**)&pOl, g_Ol);
    cudaGetSymbolAddress((void**)&pO,  g_O);

    cudaFuncSetAttribute(gemm_hmma, cudaFuncAttributeMaxDynamicSharedMemorySize, GSMEM);
    cudaFuncSetAttribute(attn_kernel, cudaFuncAttributeMaxDynamicSharedMemorySize,
                         (int)ATTN_SMEM);

    // 1. split inputs to bf16 hi/lo
    split_kernel<<<(unsigned)(((size_t)MPAD * EE) / 1024), 256>>>(
        x, pXh, pXl, (size_t)BSS * EE, (size_t)MPAD * EE);
    convw_kernel<<<NQKV, 256>>>(Wq, Wk, Wv);
    split_kernel<<<(unsigned)(((size_t)EE * EE) / 1024), 256>>>(
        Wo, pUh, pUl, (size_t)EE * EE, (size_t)EE * EE);

    // 2. fused QKV projection on HMMA tensor cores (N = 3072)
    gemm_hmma<<<dim3(MPAD / TM, NQKV / TN), 256, GSMEM>>>(
        pXh, pXl, pWh, pWl, nullptr, nullptr, 0);

    // 3. attention
    attn_kernel<<<dim3((SS + 63) / 64, HH, BB), 256, ATTN_SMEM>>>();

    // 4. split attention output, output projection on HMMA tensor cores
    split_kernel<<<(unsigned)(((size_t)MPAD * EE) / 1024), 256>>>(
        pO, pOh, pOl, (size_t)BSS * EE, (size_t)MPAD * EE);
    gemm_hmma<<<dim3(MPAD / TM, EE / TN), 256, GSMEM>>>(
        pOh, pOl, pUh, pUl, out, bo, 1);
}

// round 7
// speedup vs baseline: 2.9329x; 1.5906x over previous
#include <cuda_runtime.h>
#include <cuda_bf16.h>
#include <cstdint>

#define BB  32
#define SS  577
#define EE  1024
#define HH  16
#define DD  64
#define BSS (BB*SS)     // 18464
#define MPAD 18560      // 145*128
#define NQKV 3072
#define SPAD 640        // padded seq (5*128), multiple of key tile 64

// ---------------------------------------------------------------------------
// Device global scratch (allocation-free; statically zero-initialized)
// ---------------------------------------------------------------------------
__device__ __nv_bfloat16 g_Qh[(size_t)BB*HH*SPAD*DD];
__device__ __nv_bfloat16 g_Ql[(size_t)BB*HH*SPAD*DD];
__device__ __nv_bfloat16 g_Kh[(size_t)BB*HH*SPAD*DD];
__device__ __nv_bfloat16 g_Kl[(size_t)BB*HH*SPAD*DD];
__device__ __nv_bfloat16 g_Vh[(size_t)BB*HH*SPAD*DD];
__device__ __nv_bfloat16 g_Vl[(size_t)BB*HH*SPAD*DD];

__device__ __nv_bfloat16 g_Xh[(size_t)MPAD*EE];
__device__ __nv_bfloat16 g_Xl[(size_t)MPAD*EE];
__device__ __nv_bfloat16 g_Wh[(size_t)NQKV*EE];
__device__ __nv_bfloat16 g_Wl[(size_t)NQKV*EE];
__device__ __nv_bfloat16 g_Uh[(size_t)EE*EE];
__device__ __nv_bfloat16 g_Ul[(size_t)EE*EE];
__device__ __nv_bfloat16 g_Oh[(size_t)MPAD*EE];   // attn out (proj A), padding stays 0
__device__ __nv_bfloat16 g_Ol[(size_t)MPAD*EE];

// ---------------------------------------------------------------------------
// Helpers (sm_80-baseline PTX only — harness compiles compute_103, no tcgen05)
// ---------------------------------------------------------------------------
__device__ __forceinline__ uint32_t smem_u32(const void* p) {
    uint32_t a;
    asm("{ .reg .u64 t; cvta.to.shared.u64 t, %1; cvt.u32.u64 %0, t; }"
        : "=r"(a) : "l"(p));
    return a;
}

__device__ __forceinline__ uint32_t swz(uint32_t off) {   // SW128 XOR swizzle
    return off ^ ((off >> 3) & 0x70);
}

#define CP16(dst, src) \
    asm volatile("cp.async.cg.shared.global [%0], [%1], 16;" \
                 :: "r"(dst), "l"(src) : "memory")

#define LDSM4(r0, r1, r2, r3, addr) \
    asm volatile("ldmatrix.sync.aligned.m8n8.x4.shared.b16 {%0,%1,%2,%3}, [%4];" \
                 : "=r"(r0), "=r"(r1), "=r"(r2), "=r"(r3) : "r"(addr))

#define LDSM4T(r0, r1, r2, r3, addr) \
    asm volatile("ldmatrix.sync.aligned.m8n8.x4.trans.shared.b16 {%0,%1,%2,%3}, [%4];" \
                 : "=r"(r0), "=r"(r1), "=r"(r2), "=r"(r3) : "r"(addr))

#define MMA16816(d, a, b) \
    asm volatile("mma.sync.aligned.m16n8k16.row.col.f32.bf16.bf16.f32 " \
                 "{%0,%1,%2,%3}, {%4,%5,%6,%7}, {%8,%9}, {%0,%1,%2,%3};" \
                 : "+f"((d)[0]), "+f"((d)[1]), "+f"((d)[2]), "+f"((d)[3]) \
                 : "r"((a)[0]), "r"((a)[1]), "r"((a)[2]), "r"((a)[3]), \
                   "r"((b)[0]), "r"((b)[1]))

// pack two floats into bf16x2 hi + bf16x2 lo (lo = exact residual, rounded)
__device__ __forceinline__ void packhl(float a, float b, uint32_t& hi, uint32_t& lo) {
    __nv_bfloat16 ha = __float2bfloat16_rn(a), hb = __float2bfloat16_rn(b);
    __nv_bfloat16 la = __float2bfloat16_rn(a - __bfloat162float(ha));
    __nv_bfloat16 lb = __float2bfloat16_rn(b - __bfloat162float(hb));
    __nv_bfloat162 H = __halves2bfloat162(ha, hb);
    __nv_bfloat162 L = __halves2bfloat162(la, lb);
    hi = *(uint32_t*)&H;
    lo = *(uint32_t*)&L;
}

// ---------------------------------------------------------------------------
// fp32 -> bf16 hi/lo split (zero pad beyond n_valid)
// ---------------------------------------------------------------------------
__global__ void split_kernel(const float* __restrict__ src,
                             __nv_bfloat16* __restrict__ hd,
                             __nv_bfloat16* __restrict__ ld,
                             size_t n_valid, size_t n_total)
{
    size_t i = ((size_t)blockIdx.x * 256 + threadIdx.x) * 4;
    if (i >= n_total) return;
    float4 v = make_float4(0.f, 0.f, 0.f, 0.f);
    if (i < n_valid) v = *(const float4*)(src + i);
    uint32_t h01, l01, h23, l23;
    packhl(v.x, v.y, h01, l01);
    packhl(v.z, v.w, h23, l23);
    ((uint32_t*)hd)[(i >> 1) + 0] = h01;
    ((uint32_t*)hd)[(i >> 1) + 1] = h23;
    ((uint32_t*)ld)[(i >> 1) + 0] = l01;
    ((uint32_t*)ld)[(i >> 1) + 1] = l23;
}

// QKV weights [H][E][D] x3 -> B rows n = mat*1024 + h*64 + d, cols k = e
__global__ void convw_kernel(const float* __restrict__ Wq,
                             const float* __restrict__ Wk,
                             const float* __restrict__ Wv)
{
    int n = blockIdx.x;
    const float* W = (n < 1024) ? Wq : (n < 2048) ? Wk : Wv;
    int h = (n >> 6) & 15, d = n & 63;
    for (int k = threadIdx.x; k < EE; k += 256) {
        float v = W[((size_t)h * EE + k) * DD + d];
        __nv_bfloat16 hi = __float2bfloat16_rn(v);
        __nv_bfloat16 lo = __float2bfloat16_rn(v - __bfloat162float(hi));
        g_Wh[(size_t)n * EE + k] = hi;
        g_Wl[(size_t)n * EE + k] = lo;
    }
}

// ---------------------------------------------------------------------------
// Split-bf16 HMMA GEMM:  C[M,N] = A[M,K] * B[N,K]^T  (~fp32 accuracy)
//   mode 0: write bf16 hi/lo Q/K/V at [b,h,s,d] (SPAD stride)
//   mode 1: outp = C + bias (fp32)
// ---------------------------------------------------------------------------
#define TM 128
#define TN 128
#define KC 64
#define TILEB 16384
#define STAGEB (4*TILEB)
#define GSMEM (2*STAGEB)

__device__ __forceinline__ void issue_stage(
    uint32_t sbase,
    const __nv_bfloat16* __restrict__ Ah_, const __nv_bfloat16* __restrict__ Al_,
    const __nv_bfloat16* __restrict__ Bh_, const __nv_bfloat16* __restrict__ Bl_,
    int m0, int n0, int kt, int tid)
{
    #pragma unroll
    for (int i = 0; i < 4; i++) {
        int ff = tid + 256 * i;
        int row = ff >> 3, c = ff & 7;
        uint32_t doff = swz((uint32_t)(row * 128 + c * 16));
        size_t aoff = (size_t)(m0 + row) * EE + kt * KC + c * 8;
        size_t boff = (size_t)(n0 + row) * EE + kt * KC + c * 8;
        CP16(sbase + doff,              (const char*)(Ah_ + aoff));
        CP16(sbase + TILEB + doff,      (const char*)(Al_ + aoff));
        CP16(sbase + 2 * TILEB + doff,  (const char*)(Bh_ + boff));
        CP16(sbase + 3 * TILEB + doff,  (const char*)(Bl_ + boff));
    }
}

__device__ __forceinline__ void compute_chunk(
    uint32_t sbase, int wm, int wn, int lane, float (&acc)[2][8][4])
{
    const uint32_t aH = sbase, aL = sbase + TILEB;
    const uint32_t bH = sbase + 2 * TILEB, bL = sbase + 3 * TILEB;
    #pragma unroll
    for (int ks = 0; ks < 4; ks++) {
        uint32_t ah[2][4], al[2][4], bh[8][2], bl[8][2];
        #pragma unroll
        for (int mt = 0; mt < 2; mt++) {
            uint32_t off = swz((uint32_t)((wm + mt * 16 + (lane & 15)) * 128
                                        + (ks * 16 + (lane >> 4) * 8) * 2));
            LDSM4(ah[mt][0], ah[mt][1], ah[mt][2], ah[mt][3], aH + off);
            LDSM4(al[mt][0], al[mt][1], al[mt][2], al[mt][3], aL + off);
        }
        #pragma unroll
        for (int p = 0; p < 4; p++) {
            uint32_t off = swz((uint32_t)((wn + p * 16 + (lane & 7) + ((lane >> 4) & 1) * 8) * 128
                                        + (ks * 16 + ((lane >> 3) & 1) * 8) * 2));
            LDSM4(bh[2*p][0], bh[2*p][1], bh[2*p+1][0], bh[2*p+1][1], bH + off);
            LDSM4(bl[2*p][0], bl[2*p][1], bl[2*p+1][0], bl[2*p+1][1], bL + off);
        }
        #pragma unroll
        for (int mt = 0; mt < 2; mt++)
            #pragma unroll
            for (int nt = 0; nt < 8; nt++) {
                MMA16816(acc[mt][nt], ah[mt], bh[nt]);
                MMA16816(acc[mt][nt], al[mt], bh[nt]);
                MMA16816(acc[mt][nt], ah[mt], bl[nt]);
            }
    }
}

__global__ __launch_bounds__(256, 1)
void gemm_hmma(const __nv_bfloat16* __restrict__ Ah, const __nv_bfloat16* __restrict__ Al,
               const __nv_bfloat16* __restrict__ Bh, const __nv_bfloat16* __restrict__ Bl,
               float* __restrict__ outp, const float* __restrict__ bias, int mode)
{
    extern __shared__ __align__(1024) char smem[];
    const uint32_t sb = smem_u32(smem);
    const int tid = threadIdx.x, lane = tid & 31, wid = tid >> 5;
    const int m0 = blockIdx.x * TM, n0 = blockIdx.y * TN;
    const int wm = (wid & 3) * 32, wn = (wid >> 2) * 64;

    float acc[2][8][4];
    #pragma unroll
    for (int mt = 0; mt < 2; mt++)
        #pragma unroll
        for (int nt = 0; nt < 8; nt++)
            #pragma unroll
            for (int r = 0; r < 4; r++) acc[mt][nt][r] = 0.f;

    const int NK = EE / KC;
    issue_stage(sb, Ah, Al, Bh, Bl, m0, n0, 0, tid);
    asm volatile("cp.async.commit_group;" ::: "memory");

    int buf = 0;
    for (int kt = 0; kt < NK; kt++) {
        if (kt + 1 < NK) {
            issue_stage(sb + (buf ^ 1) * STAGEB, Ah, Al, Bh, Bl, m0, n0, kt + 1, tid);
            asm volatile("cp.async.commit_group;" ::: "memory");
            asm volatile("cp.async.wait_group 1;" ::: "memory");
        } else {
            asm volatile("cp.async.wait_group 0;" ::: "memory");
        }
        __syncthreads();
        compute_chunk(sb + buf * STAGEB, wm, wn, lane, acc);
        __syncthreads();
        buf ^= 1;
    }

    #pragma unroll
    for (int mt = 0; mt < 2; mt++) {
        #pragma unroll
        for (int half = 0; half < 2; half++) {
            int m = m0 + wm + mt * 16 + (lane >> 2) + half * 8;
            if (m >= BSS) continue;
            if (mode == 0) {
                int bb = m / SS, ss = m - bb * SS;
                #pragma unroll
                for (int nt = 0; nt < 8; nt++) {
                    int col = n0 + wn + nt * 8 + (lane & 3) * 2;
                    int mat = col >> 10, hh = (col >> 6) & 15, dd = col & 63;
                    size_t off = (((size_t)bb * HH + hh) * SPAD + ss) * DD + dd;
                    __nv_bfloat16* hp = (mat == 0 ? g_Qh : (mat == 1 ? g_Kh : g_Vh));
                    __nv_bfloat16* lp = (mat == 0 ? g_Ql : (mat == 1 ? g_Kl : g_Vl));
                    uint32_t hv, lv;
                    packhl(acc[mt][nt][half * 2 + 0], acc[mt][nt][half * 2 + 1], hv, lv);
                    *(uint32_t*)(hp + off) = hv;
                    *(uint32_t*)(lp + off) = lv;
                }
            } else {
                float* op = outp + (size_t)m * EE;
                #pragma unroll
                for (int nt = 0; nt < 8; nt++) {
                    int col = n0 + wn + nt * 8 + (lane & 3) * 2;
                    op[col]     = acc[mt][nt][half * 2 + 0] + __ldg(bias + col);
                    op[col + 1] = acc[mt][nt][half * 2 + 1] + __ldg(bias + col + 1);
                }
            }
        }
    }
}

// ---------------------------------------------------------------------------
// HMMA flash attention (FA2-style).
//   CTA: 128 queries x one (b,h). 8 warps x 16 rows. Key tiles of 64,
//   double-buffered cp.async (Kh,Kl,Vh,Vl = 32KB/stage). Q frags hoisted.
//   QK and PV both 3-term bf16 split. O written as bf16 hi/lo (proj A layout).
// ---------------------------------------------------------------------------
#define KVSTG 32768
#define ATT_SMEM (2*KVSTG)
#define NKT (SPAD/64)    // 10

__device__ __forceinline__ void attn_issue(uint32_t sbase, size_t bhq, int j0, int tid)
{
    #pragma unroll
    for (int i = 0; i < 2; i++) {
        int f = tid + 256 * i;            // 512 granules per matrix
        int row = f >> 3, c = f & 7;
        uint32_t doff = swz((uint32_t)(row * 128 + c * 16));
        size_t go = bhq + (size_t)(j0 + row) * DD + c * 8;
        CP16(sbase +          doff, (const char*)(g_Kh + go));
        CP16(sbase +  8192u + doff, (const char*)(g_Kl + go));
        CP16(sbase + 16384u + doff, (const char*)(g_Vh + go));
        CP16(sbase + 24576u + doff, (const char*)(g_Vl + go));
    }
}

__global__ __launch_bounds__(256)
void attn_hmma()
{
    extern __shared__ __align__(1024) char smem[];
    const uint32_t sb = smem_u32(smem);
    const int tid = threadIdx.x, lane = tid & 31, wid = tid >> 5;
    const int b = blockIdx.z, h = blockIdx.y, q0 = blockIdx.x * 128;
    const int wm = wid * 16;
    const size_t bh = ((size_t)b * HH + h) * SPAD * DD;

    // ---- stage Q (rows q0..q0+127, always < SPAD) through stage0, build frags
    #pragma unroll
    for (int i = 0; i < 4; i++) {
        int f = tid + 256 * i;            // 1024 granules per matrix
        int row = f >> 3, c = f & 7;
        uint32_t doff = swz((uint32_t)(row * 128 + c * 16));
        size_t go = bh + (size_t)(q0 + row) * DD + c * 8;
        CP16(sb + doff,          (const char*)(g_Qh + go));
        CP16(sb + 16384u + doff, (const char*)(g_Ql + go));
    }
    asm volatile("cp.async.commit_group;" ::: "memory");
    asm volatile("cp.async.wait_group 0;" ::: "memory");
    __syncthreads();

    uint32_t qh[4][4], ql[4][4];
    #pragma unroll
    for (int ks = 0; ks < 4; ks++) {
        uint32_t off = swz((uint32_t)((wm + (lane & 15)) * 128
                                    + (ks * 16 + (lane >> 4) * 8) * 2));
        LDSM4(qh[ks][0], qh[ks][1], qh[ks][2], qh[ks][3], sb + off);
        LDSM4(ql[ks][0], ql[ks][1], ql[ks][2], ql[ks][3], sb + 16384u + off);
    }
    __syncthreads();   // Q staging region free for KV stage0

    float o[8][4];
    #pragma unroll
    for (int nt = 0; nt < 8; nt++)
        #pragma unroll
        for (int r = 0; r < 4; r++) o[nt][r] = 0.f;
    float m0r = -1e30f, m1r = -1e30f, l0r = 0.f, l1r = 0.f;

    attn_issue(sb, bh, 0, tid);
    asm volatile("cp.async.commit_group;" ::: "memory");
    attn_issue(sb + KVSTG, bh, 64, tid);
    asm volatile("cp.async.commit_group;" ::: "memory");

    for (int t = 0; t < NKT; t++) {
        const uint32_t st = sb + (t & 1) * KVSTG;
        const int j0 = t * 64;
        if (t == NKT - 1) asm volatile("cp.async.wait_group 0;" ::: "memory");
        else              asm volatile("cp.async.wait_group 1;" ::: "memory");
        __syncthreads();

        // ---- S = Q K^T (3-term split), S tile 16q x 64keys per warp
        float s[8][4];
        #pragma unroll
        for (int nt = 0; nt < 8; nt++)
            #pragma unroll
            for (int r = 0; r < 4; r++) s[nt][r] = 0.f;

        #pragma unroll
        for (int ks = 0; ks < 4; ks++) {
            uint32_t kh[8][2], kl[8][2];
            #pragma unroll
            for (int p = 0; p < 4; p++) {
                uint32_t off = swz((uint32_t)((p * 16 + (lane & 7) + ((lane >> 4) & 1) * 8) * 128
                                            + (ks * 16 + ((lane >> 3) & 1) * 8) * 2));
                LDSM4(kh[2*p][0], kh[2*p][1], kh[2*p+1][0], kh[2*p+1][1], st + off);
                LDSM4(kl[2*p][0], kl[2*p][1], kl[2*p+1][0], kl[2*p+1][1], st + 8192u + off);
            }
            #pragma unroll
            for (int nt = 0; nt < 8; nt++) {
                MMA16816(s[nt], qh[ks], kh[nt]);
                MMA16816(s[nt], ql[ks], kh[nt]);
                MMA16816(s[nt], qh[ks], kl[nt]);
            }
        }

        // ---- scale + key mask (last tile only)
        #pragma unroll
        for (int nt = 0; nt < 8; nt++)
            #pragma unroll
            for (int r = 0; r < 4; r++) s[nt][r] *= 0.125f;
        if (j0 + 64 > SS) {
            #pragma unroll
            for (int nt = 0; nt < 8; nt++) {
                int k0 = j0 + nt * 8 + (lane & 3) * 2;
                if (k0 >= SS)     { s[nt][0] = -1e30f; s[nt][2] = -1e30f; }
                if (k0 + 1 >= SS) { s[nt][1] = -1e30f; s[nt][3] = -1e30f; }
            }
        }

        // ---- online softmax (rows r0 = lane>>2, r1 = r0+8; quad = lanes xor 1,2)
        float mx0 = -1e30f, mx1 = -1e30f;
        #pragma unroll
        for (int nt = 0; nt < 8; nt++) {
            mx0 = fmaxf(mx0, fmaxf(s[nt][0], s[nt][1]));
            mx1 = fmaxf(mx1, fmaxf(s[nt][2], s[nt][3]));
        }
        mx0 = fmaxf(mx0, __shfl_xor_sync(0xffffffffu, mx0, 1));
        mx0 = fmaxf(mx0, __shfl_xor_sync(0xffffffffu, mx0, 2));
        mx1 = fmaxf(mx1, __shfl_xor_sync(0xffffffffu, mx1, 1));
        mx1 = fmaxf(mx1, __shfl_xor_sync(0xffffffffu, mx1, 2));
        float nm0 = fmaxf(m0r, mx0), nm1 = fmaxf(m1r, mx1);
        float c0 = __expf(m0r - nm0), c1 = __expf(m1r - nm1);
        m0r = nm0; m1r = nm1;
        float sum0 = 0.f, sum1 = 0.f;
        #pragma unroll
        for (int nt = 0; nt < 8; nt++) {
            s[nt][0] = __expf(s[nt][0] - nm0); sum0 += s[nt][0];
            s[nt][1] = __expf(s[nt][1] - nm0); sum0 += s[nt][1];
            s[nt][2] = __expf(s[nt][2] - nm1); sum1 += s[nt][2];
            s[nt][3] = __expf(s[nt][3] - nm1); sum1 += s[nt][3];
        }
        sum0 += __shfl_xor_sync(0xffffffffu, sum0, 1);
        sum0 += __shfl_xor_sync(0xffffffffu, sum0, 2);
        sum1 += __shfl_xor_sync(0xffffffffu, sum1, 1);
        sum1 += __shfl_xor_sync(0xffffffffu, sum1, 2);
        l0r = l0r * c0 + sum0;
        l1r = l1r * c1 + sum1;
        #pragma unroll
        for (int nt = 0; nt < 8; nt++) {
            o[nt][0] *= c0; o[nt][1] *= c0;
            o[nt][2] *= c1; o[nt][3] *= c1;
        }

        // ---- O += P V (3-term split); P frags from S registers, V via ldmatrix.trans
        #pragma unroll
        for (int ks2 = 0; ks2 < 4; ks2++) {
            uint32_t ph[4], pl[4];
            packhl(s[2*ks2][0],   s[2*ks2][1],   ph[0], pl[0]);
            packhl(s[2*ks2][2],   s[2*ks2][3],   ph[1], pl[1]);
            packhl(s[2*ks2+1][0], s[2*ks2+1][1], ph[2], pl[2]);
            packhl(s[2*ks2+1][2], s[2*ks2+1][3], ph[3], pl[3]);

            uint32_t vh[8][2], vl[8][2];
            #pragma unroll
            for (int p = 0; p < 4; p++) {
                uint32_t off = swz((uint32_t)((ks2 * 16 + ((lane >> 3) & 1) * 8 + (lane & 7)) * 128
                                            + (p * 16 + ((lane >> 4) & 1) * 8) * 2));
                LDSM4T(vh[2*p][0], vh[2*p][1], vh[2*p+1][0], vh[2*p+1][1], st + 16384u + off);
                LDSM4T(vl[2*p][0], vl[2*p][1], vl[2*p+1][0], vl[2*p+1][1], st + 24576u + off);
            }
            #pragma unroll
            for (int nt = 0; nt < 8; nt++) {
                MMA16816(o[nt], ph, vh[nt]);
                MMA16816(o[nt], pl, vh[nt]);
                MMA16816(o[nt], ph, vl[nt]);
            }
        }
        __syncthreads();
        if (t + 2 < NKT) {
            attn_issue(st, bh, (t + 2) * 64, tid);
            asm volatile("cp.async.commit_group;" ::: "memory");
        }
    }

    // ---- epilogue: O/l -> bf16 hi/lo in proj-A layout [b*SS+s][h*64+d]
    float inv0 = 1.f / l0r, inv1 = 1.f / l1r;
    int qa = q0 + wm + (lane >> 2);
    int qb = qa + 8;
    int cb = h * DD + (lane & 3) * 2;
    if (qa < SS) {
        size_t mrow = ((size_t)b * SS + qa) * EE;
        #pragma unroll
        for (int nt = 0; nt < 8; nt++) {
            uint32_t hv, lv;
            packhl(o[nt][0] * inv0, o[nt][1] * inv0, hv, lv);
            *(uint32_t*)(g_Oh + mrow + cb + nt * 8) = hv;
            *(uint32_t*)(g_Ol + mrow + cb + nt * 8) = lv;
        }
    }
    if (qb < SS) {
        size_t mrow = ((size_t)b * SS + qb) * EE;
        #pragma unroll
        for (int nt = 0; nt < 8; nt++) {
            uint32_t hv, lv;
            packhl(o[nt][2] * inv1, o[nt][3] * inv1, hv, lv);
            *(uint32_t*)(g_Oh + mrow + cb + nt * 8) = hv;
            *(uint32_t*)(g_Ol + mrow + cb + nt * 8) = lv;
        }
    }
}

// ---------------------------------------------------------------------------
extern "C" void kernel_launch(void* const* d_in, const int* in_sizes, int n_in,
                              void* d_out, int out_size)
{
    (void)in_sizes; (void)n_in; (void)out_size;
    const float* x  = (const float*)d_in[0];
    const float* Wq = (const float*)d_in[1];
    const float* Wk = (const float*)d_in[2];
    const float* Wv = (const float*)d_in[3];
    const float* Wo = (const float*)d_in[4];
    const float* bo = (const float*)d_in[5];
    float* out = (float*)d_out;

    __nv_bfloat16 *pXh, *pXl, *pWh, *pWl, *pUh, *pUl, *pOh, *pOl;
    cudaGetSymbolAddress((void**)&pXh, g_Xh);
    cudaGetSymbolAddress((void**)&pXl, g_Xl);
    cudaGetSymbolAddress((void**)&pWh, g_Wh);
    cudaGetSymbolAddress((void**)&pWl, g_Wl);
    cudaGetSymbolAddress((void**)&pUh, g_Uh);
    cudaGetSymbolAddress((void**)&pUl, g_Ul);
    cudaGetSymbolAddress((void**)&pOh, g_Oh);
    cudaGetSymbolAddress((void**)&pOl, g_Ol);

    cudaFuncSetAttribute(gemm_hmma, cudaFuncAttributeMaxDynamicSharedMemorySize, GSMEM);
    cudaFuncSetAttribute(attn_hmma, cudaFuncAttributeMaxDynamicSharedMemorySize, ATT_SMEM);

    // 1. split inputs / weights to bf16 hi/lo
    split_kernel<<<(unsigned)(((size_t)MPAD * EE) / 1024), 256>>>(
        x, pXh, pXl, (size_t)BSS * EE, (size_t)MPAD * EE);
    convw_kernel<<<NQKV, 256>>>(Wq, Wk, Wv);
    split_kernel<<<(unsigned)(((size_t)EE * EE) / 1024), 256>>>(
        Wo, pUh, pUl, (size_t)EE * EE, (size_t)EE * EE);

    // 2. fused QKV projection -> bf16 hi/lo Q/K/V
    gemm_hmma<<<dim3(MPAD / TM, NQKV / TN), 256, GSMEM>>>(
        pXh, pXl, pWh, pWl, nullptr, nullptr, 0);

    // 3. flash attention on tensor cores -> bf16 hi/lo O
    attn_hmma<<<dim3(SPAD / 128, HH, BB), 256, ATT_SMEM>>>();

    // 4. output projection
    gemm_hmma<<<dim3(MPAD / TM, EE / TN), 256, GSMEM>>>(
        pOh, pOl, pUh, pUl, out, bo, 1);
}

// round 13
// speedup vs baseline: 3.0083x; 1.0257x over previous
#include <cuda_runtime.h>
#include <cuda_bf16.h>
#include <cstdint>

#define BB  32
#define SS  577
#define EE  1024
#define HH  16
#define DD  64
#define BSS (BB*SS)     // 18464
#define MPAD 18560      // 145*128
#define NQKV 3072
#define SPAD 640        // padded seq (5*128)

// ---------------------------------------------------------------------------
// Device global scratch (allocation-free; statically zero-initialized)
// ---------------------------------------------------------------------------
__device__ __nv_bfloat16 g_Qh[(size_t)BB*HH*SPAD*DD];
__device__ __nv_bfloat16 g_Ql[(size_t)BB*HH*SPAD*DD];
__device__ __nv_bfloat16 g_Kh[(size_t)BB*HH*SPAD*DD];
__device__ __nv_bfloat16 g_Kl[(size_t)BB*HH*SPAD*DD];
__device__ __nv_bfloat16 g_Vh[(size_t)BB*HH*SPAD*DD];
__device__ __nv_bfloat16 g_Vl[(size_t)BB*HH*SPAD*DD];

__device__ __nv_bfloat16 g_Xh[(size_t)MPAD*EE];
__device__ __nv_bfloat16 g_Xl[(size_t)MPAD*EE];
__device__ __nv_bfloat16 g_Wh[(size_t)NQKV*EE];
__device__ __nv_bfloat16 g_Wl[(size_t)NQKV*EE];
__device__ __nv_bfloat16 g_Uh[(size_t)EE*EE];
__device__ __nv_bfloat16 g_Ul[(size_t)EE*EE];
__device__ __nv_bfloat16 g_Oh[(size_t)MPAD*EE];   // attn out (proj A), padding stays 0
__device__ __nv_bfloat16 g_Ol[(size_t)MPAD*EE];

// ---------------------------------------------------------------------------
// Helpers (sm_80-baseline PTX only — harness compiles compute_103, no tcgen05)
// ---------------------------------------------------------------------------
__device__ __forceinline__ uint32_t smem_u32(const void* p) {
    uint32_t a;
    asm("{ .reg .u64 t; cvta.to.shared.u64 t, %1; cvt.u32.u64 %0, t; }"
        : "=r"(a) : "l"(p));
    return a;
}

__device__ __forceinline__ uint32_t swz(uint32_t off) {    // 128B-row swizzle
    return off ^ ((off >> 3) & 0x70);
}
__device__ __forceinline__ uint32_t swz64(uint32_t off) {  // 64B-row swizzle
    return off ^ ((off >> 3) & 0x30);
}

#define CP16(dst, src) \
    asm volatile("cp.async.cg.shared.global [%0], [%1], 16;" \
                 :: "r"(dst), "l"(src) : "memory")

#define LDSM4(r0, r1, r2, r3, addr) \
    asm volatile("ldmatrix.sync.aligned.m8n8.x4.shared.b16 {%0,%1,%2,%3}, [%4];" \
                 : "=r"(r0), "=r"(r1), "=r"(r2), "=r"(r3) : "r"(addr))

#define LDSM4T(r0, r1, r2, r3, addr) \
    asm volatile("ldmatrix.sync.aligned.m8n8.x4.trans.shared.b16 {%0,%1,%2,%3}, [%4];" \
                 : "=r"(r0), "=r"(r1), "=r"(r2), "=r"(r3) : "r"(addr))

#define MMA16816(d, a, b) \
    asm volatile("mma.sync.aligned.m16n8k16.row.col.f32.bf16.bf16.f32 " \
                 "{%0,%1,%2,%3}, {%4,%5,%6,%7}, {%8,%9}, {%0,%1,%2,%3};" \
                 : "+f"((d)[0]), "+f"((d)[1]), "+f"((d)[2]), "+f"((d)[3]) \
                 : "r"((a)[0]), "r"((a)[1]), "r"((a)[2]), "r"((a)[3]), \
                   "r"((b)[0]), "r"((b)[1]))

// pack two floats into bf16x2 hi + bf16x2 lo (lo = residual)
__device__ __forceinline__ void packhl(float a, float b, uint32_t& hi, uint32_t& lo) {
    __nv_bfloat16 ha = __float2bfloat16_rn(a), hb = __float2bfloat16_rn(b);
    __nv_bfloat16 la = __float2bfloat16_rn(a - __bfloat162float(ha));
    __nv_bfloat16 lb = __float2bfloat16_rn(b - __bfloat162float(hb));
    __nv_bfloat162 H = __halves2bfloat162(ha, hb);
    __nv_bfloat162 L = __halves2bfloat162(la, lb);
    hi = *(uint32_t*)&H;
    lo = *(uint32_t*)&L;
}

// ---------------------------------------------------------------------------
// fp32 -> bf16 hi/lo split (zero pad beyond n_valid)
// ---------------------------------------------------------------------------
__global__ void split_kernel(const float* __restrict__ src,
                             __nv_bfloat16* __restrict__ hd,
                             __nv_bfloat16* __restrict__ ld,
                             size_t n_valid, size_t n_total)
{
    size_t i = ((size_t)blockIdx.x * 256 + threadIdx.x) * 4;
    if (i >= n_total) return;
    float4 v = make_float4(0.f, 0.f, 0.f, 0.f);
    if (i < n_valid) v = *(const float4*)(src + i);
    uint32_t h01, l01, h23, l23;
    packhl(v.x, v.y, h01, l01);
    packhl(v.z, v.w, h23, l23);
    ((uint32_t*)hd)[(i >> 1) + 0] = h01;
    ((uint32_t*)hd)[(i >> 1) + 1] = h23;
    ((uint32_t*)ld)[(i >> 1) + 0] = l01;
    ((uint32_t*)ld)[(i >> 1) + 1] = l23;
}

// QKV weights [H][E][D] x3 -> B rows n = mat*1024 + h*64 + d, cols k = e
// Coalesced both sides via 64x64 smem transpose tile.
__global__ void convw_kernel(const float* __restrict__ Wq,
                             const float* __restrict__ Wk,
                             const float* __restrict__ Wv)
{
    __shared__ float t[64][65];
    const int mat = blockIdx.x, h = blockIdx.y, e0 = blockIdx.z * 64;
    const float* W = (mat == 0) ? Wq : (mat == 1) ? Wk : Wv;
    const int tid = threadIdx.x;

    // load 64 e-rows x 64 d (coalesced 256B rows), store transposed t[d][e]
    for (int i = tid; i < 64 * 64; i += 256) {
        int e = i >> 6, d = i & 63;
        t[d][e] = W[((size_t)h * EE + e0 + e) * DD + d];
    }
    __syncthreads();

    // write rows n = mat*1024 + h*64 + d, 64 contiguous e's (128B bf16 rows)
    for (int i = tid; i < 64 * 64; i += 256) {
        int d = i >> 6, e = i & 63;
        float v = t[d][e];
        __nv_bfloat16 hi = __float2bfloat16_rn(v);
        __nv_bfloat16 lo = __float2bfloat16_rn(v - __bfloat162float(hi));
        size_t off = (size_t)(mat * 1024 + h * 64 + d) * EE + e0 + e;
        g_Wh[off] = hi;
        g_Wl[off] = lo;
    }
}

// ---------------------------------------------------------------------------
// Split-bf16 HMMA GEMM:  C[M,N] = A[M,K] * B[N,K]^T  (~fp32 accuracy)
//   128x128 block, 8 warps (32m x 64n each), KC=32 chunks, 64B rows (SW64),
//   2-stage cp.async, 2 CTAs/SM (64KB smem, <=128 regs).
//   mode 0: write bf16 hi/lo Q/K/V at [b,h,s,d] (SPAD stride)
//   mode 1: outp = C + bias (fp32)
// ---------------------------------------------------------------------------
#define TM 128
#define TN 128
#define KC 32
#define TILEB 8192                     // 128 rows x 32 bf16
#define STAGEB (4*TILEB)               // Ah, Al, Bh, Bl = 32KB
#define GSMEM (2*STAGEB)               // 64KB

__device__ __forceinline__ void issue_stage(
    uint32_t sbase,
    const __nv_bfloat16* __restrict__ Ah_, const __nv_bfloat16* __restrict__ Al_,
    const __nv_bfloat16* __restrict__ Bh_, const __nv_bfloat16* __restrict__ Bl_,
    int m0, int n0, int kt, int tid)
{
    #pragma unroll
    for (int i = 0; i < 2; i++) {
        int f = tid + 256 * i;          // 512 granules per matrix
        int row = f >> 2, c = f & 3;
        uint32_t doff = swz64((uint32_t)(row * 64 + c * 16));
        size_t aoff = (size_t)(m0 + row) * EE + kt * KC + c * 8;
        size_t boff = (size_t)(n0 + row) * EE + kt * KC + c * 8;
        CP16(sbase + doff,              (const char*)(Ah_ + aoff));
        CP16(sbase + TILEB + doff,      (const char*)(Al_ + aoff));
        CP16(sbase + 2 * TILEB + doff,  (const char*)(Bh_ + boff));
        CP16(sbase + 3 * TILEB + doff,  (const char*)(Bl_ + boff));
    }
}

__device__ __forceinline__ void compute_chunk(
    uint32_t sbase, int wm, int wn, int lane, float (&acc)[2][8][4])
{
    const uint32_t aH = sbase, aL = sbase + TILEB;
    const uint32_t bH = sbase + 2 * TILEB, bL = sbase + 3 * TILEB;
    #pragma unroll
    for (int ks = 0; ks < 2; ks++) {
        uint32_t ah[2][4], al[2][4];
        #pragma unroll
        for (int mt = 0; mt < 2; mt++) {
            uint32_t off = swz64((uint32_t)((wm + mt * 16 + (lane & 15)) * 64
                                          + ks * 32 + (lane >> 4) * 16));
            LDSM4(ah[mt][0], ah[mt][1], ah[mt][2], ah[mt][3], aH + off);
            LDSM4(al[mt][0], al[mt][1], al[mt][2], al[mt][3], aL + off);
        }
        #pragma unroll
        for (int p = 0; p < 4; p++) {   // stream B frags to cap live registers
            uint32_t bh[4], bl[4];
            uint32_t off = swz64((uint32_t)((wn + p * 16 + (lane & 7) + ((lane >> 4) & 1) * 8) * 64
                                          + ks * 32 + ((lane >> 3) & 1) * 16));
            LDSM4(bh[0], bh[1], bh[2], bh[3], bH + off);
            LDSM4(bl[0], bl[1], bl[2], bl[3], bL + off);
            #pragma unroll
            for (int mt = 0; mt < 2; mt++) {
                MMA16816(acc[mt][2*p],   ah[mt], bh);
                MMA16816(acc[mt][2*p],   al[mt], bh);
                MMA16816(acc[mt][2*p],   ah[mt], bl);
                MMA16816(acc[mt][2*p+1], ah[mt], bh + 2);
                MMA16816(acc[mt][2*p+1], al[mt], bh + 2);
                MMA16816(acc[mt][2*p+1], ah[mt], bl + 2);
            }
        }
    }
}

__global__ __launch_bounds__(256, 2)
void gemm_hmma(const __nv_bfloat16* __restrict__ Ah, const __nv_bfloat16* __restrict__ Al,
               const __nv_bfloat16* __restrict__ Bh, const __nv_bfloat16* __restrict__ Bl,
               float* __restrict__ outp, const float* __restrict__ bias, int mode)
{
    extern __shared__ __align__(1024) char smem[];
    const uint32_t sb = smem_u32(smem);
    const int tid = threadIdx.x, lane = tid & 31, wid = tid >> 5;
    const int m0 = blockIdx.x * TM, n0 = blockIdx.y * TN;
    const int wm = (wid & 3) * 32, wn = (wid >> 2) * 64;

    float acc[2][8][4];
    #pragma unroll
    for (int mt = 0; mt < 2; mt++)
        #pragma unroll
        for (int nt = 0; nt < 8; nt++)
            #pragma unroll
            for (int r = 0; r < 4; r++) acc[mt][nt][r] = 0.f;

    const int NK = EE / KC;   // 32
    issue_stage(sb, Ah, Al, Bh, Bl, m0, n0, 0, tid);
    asm volatile("cp.async.commit_group;" ::: "memory");

    int buf = 0;
    for (int kt = 0; kt < NK; kt++) {
        if (kt + 1 < NK) {
            issue_stage(sb + (buf ^ 1) * STAGEB, Ah, Al, Bh, Bl, m0, n0, kt + 1, tid);
            asm volatile("cp.async.commit_group;" ::: "memory");
            asm volatile("cp.async.wait_group 1;" ::: "memory");
        } else {
            asm volatile("cp.async.wait_group 0;" ::: "memory");
        }
        __syncthreads();
        compute_chunk(sb + buf * STAGEB, wm, wn, lane, acc);
        __syncthreads();
        buf ^= 1;
    }

    #pragma unroll
    for (int mt = 0; mt < 2; mt++) {
        #pragma unroll
        for (int half = 0; half < 2; half++) {
            int m = m0 + wm + mt * 16 + (lane >> 2) + half * 8;
            if (m >= BSS) continue;
            if (mode == 0) {
                int bb = m / SS, ss = m - bb * SS;
                #pragma unroll
                for (int nt = 0; nt < 8; nt++) {
                    int col = n0 + wn + nt * 8 + (lane & 3) * 2;
                    int mat = col >> 10, hh = (col >> 6) & 15, dd = col & 63;
                    size_t off = (((size_t)bb * HH + hh) * SPAD + ss) * DD + dd;
                    __nv_bfloat16* hp = (mat == 0 ? g_Qh : (mat == 1 ? g_Kh : g_Vh));
                    __nv_bfloat16* lp = (mat == 0 ? g_Ql : (mat == 1 ? g_Kl : g_Vl));
                    uint32_t hv, lv;
                    packhl(acc[mt][nt][half * 2 + 0], acc[mt][nt][half * 2 + 1], hv, lv);
                    *(uint32_t*)(hp + off) = hv;
                    *(uint32_t*)(lp + off) = lv;
                }
            } else {
                float* op = outp + (size_t)m * EE;
                #pragma unroll
                for (int nt = 0; nt < 8; nt++) {
                    int col = n0 + wn + nt * 8 + (lane & 3) * 2;
                    op[col]     = acc[mt][nt][half * 2 + 0] + __ldg(bias + col);
                    op[col + 1] = acc[mt][nt][half * 2 + 1] + __ldg(bias + col + 1);
                }
            }
        }
    }
}

// ---------------------------------------------------------------------------
// HMMA flash attention (FA2-style, unchanged from R6-passing version).
// ---------------------------------------------------------------------------
#define KVSTG 32768
#define ATT_SMEM (2*KVSTG)
#define NKT (SPAD/64)    // 10

__device__ __forceinline__ void attn_issue(uint32_t sbase, size_t bhq, int j0, int tid)
{
    #pragma unroll
    for (int i = 0; i < 2; i++) {
        int f = tid + 256 * i;
        int row = f >> 3, c = f & 7;
        uint32_t doff = swz((uint32_t)(row * 128 + c * 16));
        size_t go = bhq + (size_t)(j0 + row) * DD + c * 8;
        CP16(sbase +          doff, (const char*)(g_Kh + go));
        CP16(sbase +  8192u + doff, (const char*)(g_Kl + go));
        CP16(sbase + 16384u + doff, (const char*)(g_Vh + go));
        CP16(sbase + 24576u + doff, (const char*)(g_Vl + go));
    }
}

__global__ __launch_bounds__(256)
void attn_hmma()
{
    extern __shared__ __align__(1024) char smem[];
    const uint32_t sb = smem_u32(smem);
    const int tid = threadIdx.x, lane = tid & 31, wid = tid >> 5;
    const int b = blockIdx.z, h = blockIdx.y, q0 = blockIdx.x * 128;
    const int wm = wid * 16;
    const size_t bh = ((size_t)b * HH + h) * SPAD * DD;

    #pragma unroll
    for (int i = 0; i < 4; i++) {
        int f = tid + 256 * i;
        int row = f >> 3, c = f & 7;
        uint32_t doff = swz((uint32_t)(row * 128 + c * 16));
        size_t go = bh + (size_t)(q0 + row) * DD + c * 8;
        CP16(sb + doff,          (const char*)(g_Qh + go));
        CP16(sb + 16384u + doff, (const char*)(g_Ql + go));
    }
    asm volatile("cp.async.commit_group;" ::: "memory");
    asm volatile("cp.async.wait_group 0;" ::: "memory");
    __syncthreads();

    uint32_t qh[4][4], ql[4][4];
    #pragma unroll
    for (int ks = 0; ks < 4; ks++) {
        uint32_t off = swz((uint32_t)((wm + (lane & 15)) * 128
                                    + (ks * 16 + (lane >> 4) * 8) * 2));
        LDSM4(qh[ks][0], qh[ks][1], qh[ks][2], qh[ks][3], sb + off);
        LDSM4(ql[ks][0], ql[ks][1], ql[ks][2], ql[ks][3], sb + 16384u + off);
    }
    __syncthreads();

    float o[8][4];
    #pragma unroll
    for (int nt = 0; nt < 8; nt++)
        #pragma unroll
        for (int r = 0; r < 4; r++) o[nt][r] = 0.f;
    float m0r = -1e30f, m1r = -1e30f, l0r = 0.f, l1r = 0.f;

    attn_issue(sb, bh, 0, tid);
    asm volatile("cp.async.commit_group;" ::: "memory");
    attn_issue(sb + KVSTG, bh, 64, tid);
    asm volatile("cp.async.commit_group;" ::: "memory");

    for (int t = 0; t < NKT; t++) {
        const uint32_t st = sb + (t & 1) * KVSTG;
        const int j0 = t * 64;
        if (t == NKT - 1) asm volatile("cp.async.wait_group 0;" ::: "memory");
        else              asm volatile("cp.async.wait_group 1;" ::: "memory");
        __syncthreads();

        float s[8][4];
        #pragma unroll
        for (int nt = 0; nt < 8; nt++)
            #pragma unroll
            for (int r = 0; r < 4; r++) s[nt][r] = 0.f;

        #pragma unroll
        for (int ks = 0; ks < 4; ks++) {
            uint32_t kh[8][2], kl[8][2];
            #pragma unroll
            for (int p = 0; p < 4; p++) {
                uint32_t off = swz((uint32_t)((p * 16 + (lane & 7) + ((lane >> 4) & 1) * 8) * 128
                                            + (ks * 16 + ((lane >> 3) & 1) * 8) * 2));
                LDSM4(kh[2*p][0], kh[2*p][1], kh[2*p+1][0], kh[2*p+1][1], st + off);
                LDSM4(kl[2*p][0], kl[2*p][1], kl[2*p+1][0], kl[2*p+1][1], st + 8192u + off);
            }
            #pragma unroll
            for (int nt = 0; nt < 8; nt++) {
                MMA16816(s[nt], qh[ks], kh[nt]);
                MMA16816(s[nt], ql[ks], kh[nt]);
                MMA16816(s[nt], qh[ks], kl[nt]);
            }
        }

        #pragma unroll
        for (int nt = 0; nt < 8; nt++)
            #pragma unroll
            for (int r = 0; r < 4; r++) s[nt][r] *= 0.125f;
        if (j0 + 64 > SS) {
            #pragma unroll
            for (int nt = 0; nt < 8; nt++) {
                int k0 = j0 + nt * 8 + (lane & 3) * 2;
                if (k0 >= SS)     { s[nt][0] = -1e30f; s[nt][2] = -1e30f; }
                if (k0 + 1 >= SS) { s[nt][1] = -1e30f; s[nt][3] = -1e30f; }
            }
        }

        float mx0 = -1e30f, mx1 = -1e30f;
        #pragma unroll
        for (int nt = 0; nt < 8; nt++) {
            mx0 = fmaxf(mx0, fmaxf(s[nt][0], s[nt][1]));
            mx1 = fmaxf(mx1, fmaxf(s[nt][2], s[nt][3]));
        }
        mx0 = fmaxf(mx0, __shfl_xor_sync(0xffffffffu, mx0, 1));
        mx0 = fmaxf(mx0, __shfl_xor_sync(0xffffffffu, mx0, 2));
        mx1 = fmaxf(mx1, __shfl_xor_sync(0xffffffffu, mx1, 1));
        mx1 = fmaxf(mx1, __shfl_xor_sync(0xffffffffu, mx1, 2));
        float nm0 = fmaxf(m0r, mx0), nm1 = fmaxf(m1r, mx1);
        float c0 = __expf(m0r - nm0), c1 = __expf(m1r - nm1);
        m0r = nm0; m1r = nm1;
        float sum0 = 0.f, sum1 = 0.f;
        #pragma unroll
        for (int nt = 0; nt < 8; nt++) {
            s[nt][0] = __expf(s[nt][0] - nm0); sum0 += s[nt][0];
            s[nt][1] = __expf(s[nt][1] - nm0); sum0 += s[nt][1];
            s[nt][2] = __expf(s[nt][2] - nm1); sum1 += s[nt][2];
            s[nt][3] = __expf(s[nt][3] - nm1); sum1 += s[nt][3];
        }
        sum0 += __shfl_xor_sync(0xffffffffu, sum0, 1);
        sum0 += __shfl_xor_sync(0xffffffffu, sum0, 2);
        sum1 += __shfl_xor_sync(0xffffffffu, sum1, 1);
        sum1 += __shfl_xor_sync(0xffffffffu, sum1, 2);
        l0r = l0r * c0 + sum0;
        l1r = l1r * c1 + sum1;
        #pragma unroll
        for (int nt = 0; nt < 8; nt++) {
            o[nt][0] *= c0; o[nt][1] *= c0;
            o[nt][2] *= c1; o[nt][3] *= c1;
        }

        #pragma unroll
        for (int ks2 = 0; ks2 < 4; ks2++) {
            uint32_t ph[4], pl[4];
            packhl(s[2*ks2][0],   s[2*ks2][1],   ph[0], pl[0]);
            packhl(s[2*ks2][2],   s[2*ks2][3],   ph[1], pl[1]);
            packhl(s[2*ks2+1][0], s[2*ks2+1][1], ph[2], pl[2]);
            packhl(s[2*ks2+1][2], s[2*ks2+1][3], ph[3], pl[3]);

            uint32_t vh[8][2], vl[8][2];
            #pragma unroll
            for (int p = 0; p < 4; p++) {
                uint32_t off = swz((uint32_t)((ks2 * 16 + ((lane >> 3) & 1) * 8 + (lane & 7)) * 128
                                            + (p * 16 + ((lane >> 4) & 1) * 8) * 2));
                LDSM4T(vh[2*p][0], vh[2*p][1], vh[2*p+1][0], vh[2*p+1][1], st + 16384u + off);
                LDSM4T(vl[2*p][0], vl[2*p][1], vl[2*p+1][0], vl[2*p+1][1], st + 24576u + off);
            }
            #pragma unroll
            for (int nt = 0; nt < 8; nt++) {
                MMA16816(o[nt], ph, vh[nt]);
                MMA16816(o[nt], pl, vh[nt]);
                MMA16816(o[nt], ph, vl[nt]);
            }
        }
        __syncthreads();
        if (t + 2 < NKT) {
            attn_issue(st, bh, (t + 2) * 64, tid);
            asm volatile("cp.async.commit_group;" ::: "memory");
        }
    }

    float inv0 = 1.f / l0r, inv1 = 1.f / l1r;
    int qa = q0 + wm + (lane >> 2);
    int qb = qa + 8;
    int cb = h * DD + (lane & 3) * 2;
    if (qa < SS) {
        size_t mrow = ((size_t)b * SS + qa) * EE;
        #pragma unroll
        for (int nt = 0; nt < 8; nt++) {
            uint32_t hv, lv;
            packhl(o[nt][0] * inv0, o[nt][1] * inv0, hv, lv);
            *(uint32_t*)(g_Oh + mrow + cb + nt * 8) = hv;
            *(uint32_t*)(g_Ol + mrow + cb + nt * 8) = lv;
        }
    }
    if (qb < SS) {
        size_t mrow = ((size_t)b * SS + qb) * EE;
        #pragma unroll
        for (int nt = 0; nt < 8; nt++) {
            uint32_t hv, lv;
            packhl(o[nt][2] * inv1, o[nt][3] * inv1, hv, lv);
            *(uint32_t*)(g_Oh + mrow + cb + nt * 8) = hv;
            *(uint32_t*)(g_Ol + mrow + cb + nt * 8) = lv;
        }
    }
}

// ---------------------------------------------------------------------------
extern "C" void kernel_launch(void* const* d_in, const int* in_sizes, int n_in,
                              void* d_out, int out_size)
{
    (void)in_sizes; (void)n_in; (void)out_size;
    const float* x  = (const float*)d_in[0];
    const float* Wq = (const float*)d_in[1];
    const float* Wk = (const float*)d_in[2];
    const float* Wv = (const float*)d_in[3];
    const float* Wo = (const float*)d_in[4];
    const float* bo = (const float*)d_in[5];
    float* out = (float*)d_out;

    __nv_bfloat16 *pXh, *pXl, *pWh, *pWl, *pUh, *pUl, *pOh, *pOl;
    cudaGetSymbolAddress((void**)&pXh, g_Xh);
    cudaGetSymbolAddress((void**)&pXl, g_Xl);
    cudaGetSymbolAddress((void**)&pWh, g_Wh);
    cudaGetSymbolAddress((void**)&pWl, g_Wl);
    cudaGetSymbolAddress((void**)&pUh, g_Uh);
    cudaGetSymbolAddress((void**)&pUl, g_Ul);
    cudaGetSymbolAddress((void**)&pOh, g_Oh);
    cudaGetSymbolAddress((void**)&pOl, g_Ol);

    cudaFuncSetAttribute(gemm_hmma, cudaFuncAttributeMaxDynamicSharedMemorySize, GSMEM);
    cudaFuncSetAttribute(attn_hmma, cudaFuncAttributeMaxDynamicSharedMemorySize, ATT_SMEM);

    // 1. split inputs / weights to bf16 hi/lo
    split_kernel<<<(unsigned)(((size_t)MPAD * EE) / 1024), 256>>>(
        x, pXh, pXl, (size_t)BSS * EE, (size_t)MPAD * EE);
    convw_kernel<<<dim3(3, HH, EE / 64), 256>>>(Wq, Wk, Wv);
    split_kernel<<<(unsigned)(((size_t)EE * EE) / 1024), 256>>>(
        Wo, pUh, pUl, (size_t)EE * EE, (size_t)EE * EE);

    // 2. fused QKV projection -> bf16 hi/lo Q/K/V
    gemm_hmma<<<dim3(MPAD / TM, NQKV / TN), 256, GSMEM>>>(
        pXh, pXl, pWh, pWl, nullptr, nullptr, 0);

    // 3. flash attention on tensor cores -> bf16 hi/lo O
    attn_hmma<<<dim3(SPAD / 128, HH, BB), 256, ATT_SMEM>>>();

    // 4. output projection
    gemm_hmma<<<dim3(MPAD / TM, EE / TN), 256, GSMEM>>>(
        pOh, pOl, pUh, pUl, out, bo, 1);
}

// round 14
// speedup vs baseline: 3.0517x; 1.0144x over previous
#include <cuda_runtime.h>
#include <cuda_bf16.h>
#include <cstdint>

#define BB  32
#define SS  577
#define EE  1024
#define HH  16
#define DD  64
#define BSS (BB*SS)     // 18464
#define MPAD 18560      // 145*128
#define NQKV 3072
#define SPAD 640        // padded seq (5*128)

// ---------------------------------------------------------------------------
// Device global scratch (allocation-free; statically zero-initialized)
// ---------------------------------------------------------------------------
__device__ __nv_bfloat16 g_Qh[(size_t)BB*HH*SPAD*DD];
__device__ __nv_bfloat16 g_Ql[(size_t)BB*HH*SPAD*DD];
__device__ __nv_bfloat16 g_Kh[(size_t)BB*HH*SPAD*DD];
__device__ __nv_bfloat16 g_Kl[(size_t)BB*HH*SPAD*DD];
__device__ __nv_bfloat16 g_Vh[(size_t)BB*HH*SPAD*DD];
__device__ __nv_bfloat16 g_Vl[(size_t)BB*HH*SPAD*DD];

__device__ __nv_bfloat16 g_Xh[(size_t)MPAD*EE];
__device__ __nv_bfloat16 g_Xl[(size_t)MPAD*EE];
__device__ __nv_bfloat16 g_Wh[(size_t)NQKV*EE];
__device__ __nv_bfloat16 g_Wl[(size_t)NQKV*EE];
__device__ __nv_bfloat16 g_Uh[(size_t)EE*EE];
__device__ __nv_bfloat16 g_Ul[(size_t)EE*EE];
__device__ __nv_bfloat16 g_Oh[(size_t)MPAD*EE];   // attn out (proj A), padding stays 0
__device__ __nv_bfloat16 g_Ol[(size_t)MPAD*EE];

// ---------------------------------------------------------------------------
// Helpers (sm_80-baseline PTX only — harness compiles compute_103, no tcgen05)
// ---------------------------------------------------------------------------
__device__ __forceinline__ uint32_t smem_u32(const void* p) {
    uint32_t a;
    asm("{ .reg .u64 t; cvta.to.shared.u64 t, %1; cvt.u32.u64 %0, t; }"
        : "=r"(a) : "l"(p));
    return a;
}

__device__ __forceinline__ uint32_t swz(uint32_t off) {    // 128B-row swizzle
    return off ^ ((off >> 3) & 0x70);
}
__device__ __forceinline__ uint32_t swz64(uint32_t off) {  // 64B-row swizzle
    return off ^ ((off >> 3) & 0x30);
}

#define CP16(dst, src) \
    asm volatile("cp.async.cg.shared.global [%0], [%1], 16;" \
                 :: "r"(dst), "l"(src) : "memory")

#define LDSM4(r0, r1, r2, r3, addr) \
    asm volatile("ldmatrix.sync.aligned.m8n8.x4.shared.b16 {%0,%1,%2,%3}, [%4];" \
                 : "=r"(r0), "=r"(r1), "=r"(r2), "=r"(r3) : "r"(addr))

#define LDSM4T(r0, r1, r2, r3, addr) \
    asm volatile("ldmatrix.sync.aligned.m8n8.x4.trans.shared.b16 {%0,%1,%2,%3}, [%4];" \
                 : "=r"(r0), "=r"(r1), "=r"(r2), "=r"(r3) : "r"(addr))

#define MMA16816(d, a, b) \
    asm volatile("mma.sync.aligned.m16n8k16.row.col.f32.bf16.bf16.f32 " \
                 "{%0,%1,%2,%3}, {%4,%5,%6,%7}, {%8,%9}, {%0,%1,%2,%3};" \
                 : "+f"((d)[0]), "+f"((d)[1]), "+f"((d)[2]), "+f"((d)[3]) \
                 : "r"((a)[0]), "r"((a)[1]), "r"((a)[2]), "r"((a)[3]), \
                   "r"((b)[0]), "r"((b)[1]))

// pack two floats into bf16x2 hi + bf16x2 lo (lo = residual)
__device__ __forceinline__ void packhl(float a, float b, uint32_t& hi, uint32_t& lo) {
    __nv_bfloat16 ha = __float2bfloat16_rn(a), hb = __float2bfloat16_rn(b);
    __nv_bfloat16 la = __float2bfloat16_rn(a - __bfloat162float(ha));
    __nv_bfloat16 lb = __float2bfloat16_rn(b - __bfloat162float(hb));
    __nv_bfloat162 H = __halves2bfloat162(ha, hb);
    __nv_bfloat162 L = __halves2bfloat162(la, lb);
    hi = *(uint32_t*)&H;
    lo = *(uint32_t*)&L;
}

// ---------------------------------------------------------------------------
// fp32 -> bf16 hi/lo split (zero pad beyond n_valid)
// ---------------------------------------------------------------------------
__global__ void split_kernel(const float* __restrict__ src,
                             __nv_bfloat16* __restrict__ hd,
                             __nv_bfloat16* __restrict__ ld,
                             size_t n_valid, size_t n_total)
{
    size_t i = ((size_t)blockIdx.x * 256 + threadIdx.x) * 4;
    if (i >= n_total) return;
    float4 v = make_float4(0.f, 0.f, 0.f, 0.f);
    if (i < n_valid) v = *(const float4*)(src + i);
    uint32_t h01, l01, h23, l23;
    packhl(v.x, v.y, h01, l01);
    packhl(v.z, v.w, h23, l23);
    ((uint32_t*)hd)[(i >> 1) + 0] = h01;
    ((uint32_t*)hd)[(i >> 1) + 1] = h23;
    ((uint32_t*)ld)[(i >> 1) + 0] = l01;
    ((uint32_t*)ld)[(i >> 1) + 1] = l23;
}

// QKV weights [H][E][D] x3 -> B rows n = mat*1024 + h*64 + d, cols k = e
// Coalesced both sides via 64x64 smem transpose tile.
__global__ void convw_kernel(const float* __restrict__ Wq,
                             const float* __restrict__ Wk,
                             const float* __restrict__ Wv)
{
    __shared__ float t[64][65];
    const int mat = blockIdx.x, h = blockIdx.y, e0 = blockIdx.z * 64;
    const float* W = (mat == 0) ? Wq : (mat == 1) ? Wk : Wv;
    const int tid = threadIdx.x;

    for (int i = tid; i < 64 * 64; i += 256) {
        int e = i >> 6, d = i & 63;
        t[d][e] = W[((size_t)h * EE + e0 + e) * DD + d];
    }
    __syncthreads();

    for (int i = tid; i < 64 * 64; i += 256) {
        int d = i >> 6, e = i & 63;
        float v = t[d][e];
        __nv_bfloat16 hi = __float2bfloat16_rn(v);
        __nv_bfloat16 lo = __float2bfloat16_rn(v - __bfloat162float(hi));
        size_t off = (size_t)(mat * 1024 + h * 64 + d) * EE + e0 + e;
        g_Wh[off] = hi;
        g_Wl[off] = lo;
    }
}

// ---------------------------------------------------------------------------
// Split-bf16 HMMA GEMM:  C[M,N] = A[M,K] * B[N,K]^T  (~fp32 accuracy)
//   128x128 block, 8 warps (32m x 64n each), KC=32 chunks, 64B rows (SW64),
//   2-stage cp.async, 2 CTAs/SM. MMA issue is TERM-MAJOR: same-accumulator
//   reuse distance 4 (was 1) to break HMMA dependency stalls.
// ---------------------------------------------------------------------------
#define TM 128
#define TN 128
#define KC 32
#define TILEB 8192                     // 128 rows x 32 bf16
#define STAGEB (4*TILEB)               // Ah, Al, Bh, Bl = 32KB
#define GSMEM (2*STAGEB)               // 64KB

__device__ __forceinline__ void issue_stage(
    uint32_t sbase,
    const __nv_bfloat16* __restrict__ Ah_, const __nv_bfloat16* __restrict__ Al_,
    const __nv_bfloat16* __restrict__ Bh_, const __nv_bfloat16* __restrict__ Bl_,
    int m0, int n0, int kt, int tid)
{
    #pragma unroll
    for (int i = 0; i < 2; i++) {
        int f = tid + 256 * i;          // 512 granules per matrix
        int row = f >> 2, c = f & 3;
        uint32_t doff = swz64((uint32_t)(row * 64 + c * 16));
        size_t aoff = (size_t)(m0 + row) * EE + kt * KC + c * 8;
        size_t boff = (size_t)(n0 + row) * EE + kt * KC + c * 8;
        CP16(sbase + doff,              (const char*)(Ah_ + aoff));
        CP16(sbase + TILEB + doff,      (const char*)(Al_ + aoff));
        CP16(sbase + 2 * TILEB + doff,  (const char*)(Bh_ + boff));
        CP16(sbase + 3 * TILEB + doff,  (const char*)(Bl_ + boff));
    }
}

__device__ __forceinline__ void compute_chunk(
    uint32_t sbase, int wm, int wn, int lane, float (&acc)[2][8][4])
{
    const uint32_t aH = sbase, aL = sbase + TILEB;
    const uint32_t bH = sbase + 2 * TILEB, bL = sbase + 3 * TILEB;
    #pragma unroll
    for (int ks = 0; ks < 2; ks++) {
        uint32_t ah[2][4], al[2][4];
        #pragma unroll
        for (int mt = 0; mt < 2; mt++) {
            uint32_t off = swz64((uint32_t)((wm + mt * 16 + (lane & 15)) * 64
                                          + ks * 32 + (lane >> 4) * 16));
            LDSM4(ah[mt][0], ah[mt][1], ah[mt][2], ah[mt][3], aH + off);
            LDSM4(al[mt][0], al[mt][1], al[mt][2], al[mt][3], aL + off);
        }
        #pragma unroll
        for (int p = 0; p < 4; p++) {
            uint32_t bh[4], bl[4];
            uint32_t off = swz64((uint32_t)((wn + p * 16 + (lane & 7) + ((lane >> 4) & 1) * 8) * 64
                                          + ks * 32 + ((lane >> 3) & 1) * 16));
            LDSM4(bh[0], bh[1], bh[2], bh[3], bH + off);
            LDSM4(bl[0], bl[1], bl[2], bl[3], bL + off);
            // term-major: same-acc reuse distance = 4 (was 1)
            MMA16816(acc[0][2*p],   ah[0], bh);
            MMA16816(acc[1][2*p],   ah[1], bh);
            MMA16816(acc[0][2*p+1], ah[0], bh + 2);
            MMA16816(acc[1][2*p+1], ah[1], bh + 2);

            MMA16816(acc[0][2*p],   al[0], bh);
            MMA16816(acc[1][2*p],   al[1], bh);
            MMA16816(acc[0][2*p+1], al[0], bh + 2);
            MMA16816(acc[1][2*p+1], al[1], bh + 2);

            MMA16816(acc[0][2*p],   ah[0], bl);
            MMA16816(acc[1][2*p],   ah[1], bl);
            MMA16816(acc[0][2*p+1], ah[0], bl + 2);
            MMA16816(acc[1][2*p+1], ah[1], bl + 2);
        }
    }
}

__global__ __launch_bounds__(256, 2)
void gemm_hmma(const __nv_bfloat16* __restrict__ Ah, const __nv_bfloat16* __restrict__ Al,
               const __nv_bfloat16* __restrict__ Bh, const __nv_bfloat16* __restrict__ Bl,
               float* __restrict__ outp, const float* __restrict__ bias, int mode)
{
    extern __shared__ __align__(1024) char smem[];
    const uint32_t sb = smem_u32(smem);
    const int tid = threadIdx.x, lane = tid & 31, wid = tid >> 5;
    const int m0 = blockIdx.x * TM, n0 = blockIdx.y * TN;
    const int wm = (wid & 3) * 32, wn = (wid >> 2) * 64;

    float acc[2][8][4];
    #pragma unroll
    for (int mt = 0; mt < 2; mt++)
        #pragma unroll
        for (int nt = 0; nt < 8; nt++)
            #pragma unroll
            for (int r = 0; r < 4; r++) acc[mt][nt][r] = 0.f;

    const int NK = EE / KC;   // 32
    issue_stage(sb, Ah, Al, Bh, Bl, m0, n0, 0, tid);
    asm volatile("cp.async.commit_group;" ::: "memory");

    int buf = 0;
    for (int kt = 0; kt < NK; kt++) {
        if (kt + 1 < NK) {
            issue_stage(sb + (buf ^ 1) * STAGEB, Ah, Al, Bh, Bl, m0, n0, kt + 1, tid);
            asm volatile("cp.async.commit_group;" ::: "memory");
            asm volatile("cp.async.wait_group 1;" ::: "memory");
        } else {
            asm volatile("cp.async.wait_group 0;" ::: "memory");
        }
        __syncthreads();
        compute_chunk(sb + buf * STAGEB, wm, wn, lane, acc);
        __syncthreads();
        buf ^= 1;
    }

    #pragma unroll
    for (int mt = 0; mt < 2; mt++) {
        #pragma unroll
        for (int half = 0; half < 2; half++) {
            int m = m0 + wm + mt * 16 + (lane >> 2) + half * 8;
            if (m >= BSS) continue;
            if (mode == 0) {
                int bb = m / SS, ss = m - bb * SS;
                #pragma unroll
                for (int nt = 0; nt < 8; nt++) {
                    int col = n0 + wn + nt * 8 + (lane & 3) * 2;
                    int mat = col >> 10, hh = (col >> 6) & 15, dd = col & 63;
                    size_t off = (((size_t)bb * HH + hh) * SPAD + ss) * DD + dd;
                    __nv_bfloat16* hp = (mat == 0 ? g_Qh : (mat == 1 ? g_Kh : g_Vh));
                    __nv_bfloat16* lp = (mat == 0 ? g_Ql : (mat == 1 ? g_Kl : g_Vl));
                    uint32_t hv, lv;
                    packhl(acc[mt][nt][half * 2 + 0], acc[mt][nt][half * 2 + 1], hv, lv);
                    *(uint32_t*)(hp + off) = hv;
                    *(uint32_t*)(lp + off) = lv;
                }
            } else {
                float* op = outp + (size_t)m * EE;
                #pragma unroll
                for (int nt = 0; nt < 8; nt++) {
                    int col = n0 + wn + nt * 8 + (lane & 3) * 2;
                    op[col]     = acc[mt][nt][half * 2 + 0] + __ldg(bias + col);
                    op[col + 1] = acc[mt][nt][half * 2 + 1] + __ldg(bias + col + 1);
                }
            }
        }
    }
}

// ---------------------------------------------------------------------------
// HMMA flash attention (FA2-style) — MMA issue reordered term-major:
// same-acc reuse distance 8 for both QK and PV loops.
// ---------------------------------------------------------------------------
#define KVSTG 32768
#define ATT_SMEM (2*KVSTG)
#define NKT (SPAD/64)    // 10

__device__ __forceinline__ void attn_issue(uint32_t sbase, size_t bhq, int j0, int tid)
{
    #pragma unroll
    for (int i = 0; i < 2; i++) {
        int f = tid + 256 * i;
        int row = f >> 3, c = f & 7;
        uint32_t doff = swz((uint32_t)(row * 128 + c * 16));
        size_t go = bhq + (size_t)(j0 + row) * DD + c * 8;
        CP16(sbase +          doff, (const char*)(g_Kh + go));
        CP16(sbase +  8192u + doff, (const char*)(g_Kl + go));
        CP16(sbase + 16384u + doff, (const char*)(g_Vh + go));
        CP16(sbase + 24576u + doff, (const char*)(g_Vl + go));
    }
}

__global__ __launch_bounds__(256)
void attn_hmma()
{
    extern __shared__ __align__(1024) char smem[];
    const uint32_t sb = smem_u32(smem);
    const int tid = threadIdx.x, lane = tid & 31, wid = tid >> 5;
    const int b = blockIdx.z, h = blockIdx.y, q0 = blockIdx.x * 128;
    const int wm = wid * 16;
    const size_t bh = ((size_t)b * HH + h) * SPAD * DD;

    #pragma unroll
    for (int i = 0; i < 4; i++) {
        int f = tid + 256 * i;
        int row = f >> 3, c = f & 7;
        uint32_t doff = swz((uint32_t)(row * 128 + c * 16));
        size_t go = bh + (size_t)(q0 + row) * DD + c * 8;
        CP16(sb + doff,          (const char*)(g_Qh + go));
        CP16(sb + 16384u + doff, (const char*)(g_Ql + go));
    }
    asm volatile("cp.async.commit_group;" ::: "memory");
    asm volatile("cp.async.wait_group 0;" ::: "memory");
    __syncthreads();

    uint32_t qh[4][4], ql[4][4];
    #pragma unroll
    for (int ks = 0; ks < 4; ks++) {
        uint32_t off = swz((uint32_t)((wm + (lane & 15)) * 128
                                    + (ks * 16 + (lane >> 4) * 8) * 2));
        LDSM4(qh[ks][0], qh[ks][1], qh[ks][2], qh[ks][3], sb + off);
        LDSM4(ql[ks][0], ql[ks][1], ql[ks][2], ql[ks][3], sb + 16384u + off);
    }
    __syncthreads();

    float o[8][4];
    #pragma unroll
    for (int nt = 0; nt < 8; nt++)
        #pragma unroll
        for (int r = 0; r < 4; r++) o[nt][r] = 0.f;
    float m0r = -1e30f, m1r = -1e30f, l0r = 0.f, l1r = 0.f;

    attn_issue(sb, bh, 0, tid);
    asm volatile("cp.async.commit_group;" ::: "memory");
    attn_issue(sb + KVSTG, bh, 64, tid);
    asm volatile("cp.async.commit_group;" ::: "memory");

    for (int t = 0; t < NKT; t++) {
        const uint32_t st = sb + (t & 1) * KVSTG;
        const int j0 = t * 64;
        if (t == NKT - 1) asm volatile("cp.async.wait_group 0;" ::: "memory");
        else              asm volatile("cp.async.wait_group 1;" ::: "memory");
        __syncthreads();

        float s[8][4];
        #pragma unroll
        for (int nt = 0; nt < 8; nt++)
            #pragma unroll
            for (int r = 0; r < 4; r++) s[nt][r] = 0.f;

        #pragma unroll
        for (int ks = 0; ks < 4; ks++) {
            uint32_t kh[8][2], kl[8][2];
            #pragma unroll
            for (int p = 0; p < 4; p++) {
                uint32_t off = swz((uint32_t)((p * 16 + (lane & 7) + ((lane >> 4) & 1) * 8) * 128
                                            + (ks * 16 + ((lane >> 3) & 1) * 8) * 2));
                LDSM4(kh[2*p][0], kh[2*p][1], kh[2*p+1][0], kh[2*p+1][1], st + off);
                LDSM4(kl[2*p][0], kl[2*p][1], kl[2*p+1][0], kl[2*p+1][1], st + 8192u + off);
            }
            // term-major: same s[nt] reuse distance 8 (was 1)
            #pragma unroll
            for (int nt = 0; nt < 8; nt++) MMA16816(s[nt], qh[ks], kh[nt]);
            #pragma unroll
            for (int nt = 0; nt < 8; nt++) MMA16816(s[nt], ql[ks], kh[nt]);
            #pragma unroll
            for (int nt = 0; nt < 8; nt++) MMA16816(s[nt], qh[ks], kl[nt]);
        }

        #pragma unroll
        for (int nt = 0; nt < 8; nt++)
            #pragma unroll
            for (int r = 0; r < 4; r++) s[nt][r] *= 0.125f;
        if (j0 + 64 > SS) {
            #pragma unroll
            for (int nt = 0; nt < 8; nt++) {
                int k0 = j0 + nt * 8 + (lane & 3) * 2;
                if (k0 >= SS)     { s[nt][0] = -1e30f; s[nt][2] = -1e30f; }
                if (k0 + 1 >= SS) { s[nt][1] = -1e30f; s[nt][3] = -1e30f; }
            }
        }

        float mx0 = -1e30f, mx1 = -1e30f;
        #pragma unroll
        for (int nt = 0; nt < 8; nt++) {
            mx0 = fmaxf(mx0, fmaxf(s[nt][0], s[nt][1]));
            mx1 = fmaxf(mx1, fmaxf(s[nt][2], s[nt][3]));
        }
        mx0 = fmaxf(mx0, __shfl_xor_sync(0xffffffffu, mx0, 1));
        mx0 = fmaxf(mx0, __shfl_xor_sync(0xffffffffu, mx0, 2));
        mx1 = fmaxf(mx1, __shfl_xor_sync(0xffffffffu, mx1, 1));
        mx1 = fmaxf(mx1, __shfl_xor_sync(0xffffffffu, mx1, 2));
        float nm0 = fmaxf(m0r, mx0), nm1 = fmaxf(m1r, mx1);
        float c0 = __expf(m0r - nm0), c1 = __expf(m1r - nm1);
        m0r = nm0; m1r = nm1;
        float sum0 = 0.f, sum1 = 0.f;
        #pragma unroll
        for (int nt = 0; nt < 8; nt++) {
            s[nt][0] = __expf(s[nt][0] - nm0); sum0 += s[nt][0];
            s[nt][1] = __expf(s[nt][1] - nm0); sum0 += s[nt][1];
            s[nt][2] = __expf(s[nt][2] - nm1); sum1 += s[nt][2];
            s[nt][3] = __expf(s[nt][3] - nm1); sum1 += s[nt][3];
        }
        sum0 += __shfl_xor_sync(0xffffffffu, sum0, 1);
        sum0 += __shfl_xor_sync(0xffffffffu, sum0, 2);
        sum1 += __shfl_xor_sync(0xffffffffu, sum1, 1);
        sum1 += __shfl_xor_sync(0xffffffffu, sum1, 2);
        l0r = l0r * c0 + sum0;
        l1r = l1r * c1 + sum1;
        #pragma unroll
        for (int nt = 0; nt < 8; nt++) {
            o[nt][0] *= c0; o[nt][1] *= c0;
            o[nt][2] *= c1; o[nt][3] *= c1;
        }

        #pragma unroll
        for (int ks2 = 0; ks2 < 4; ks2++) {
            uint32_t ph[4], pl[4];
            packhl(s[2*ks2][0],   s[2*ks2][1],   ph[0], pl[0]);
            packhl(s[2*ks2][2],   s[2*ks2][3],   ph[1], pl[1]);
            packhl(s[2*ks2+1][0], s[2*ks2+1][1], ph[2], pl[2]);
            packhl(s[2*ks2+1][2], s[2*ks2+1][3], ph[3], pl[3]);

            uint32_t vh[8][2], vl[8][2];
            #pragma unroll
            for (int p = 0; p < 4; p++) {
                uint32_t off = swz((uint32_t)((ks2 * 16 + ((lane >> 3) & 1) * 8 + (lane & 7)) * 128
                                            + (p * 16 + ((lane >> 4) & 1) * 8) * 2));
                LDSM4T(vh[2*p][0], vh[2*p][1], vh[2*p+1][0], vh[2*p+1][1], st + 16384u + off);
                LDSM4T(vl[2*p][0], vl[2*p][1], vl[2*p+1][0], vl[2*p+1][1], st + 24576u + off);
            }
            // term-major: same o[nt] reuse distance 8 (was 1)
            #pragma unroll
            for (int nt = 0; nt < 8; nt++) MMA16816(o[nt], ph, vh[nt]);
            #pragma unroll
            for (int nt = 0; nt < 8; nt++) MMA16816(o[nt], pl, vh[nt]);
            #pragma unroll
            for (int nt = 0; nt < 8; nt++) MMA16816(o[nt], ph, vl[nt]);
        }
        __syncthreads();
        if (t + 2 < NKT) {
            attn_issue(st, bh, (t + 2) * 64, tid);
            asm volatile("cp.async.commit_group;" ::: "memory");
        }
    }

    float inv0 = 1.f / l0r, inv1 = 1.f / l1r;
    int qa = q0 + wm + (lane >> 2);
    int qb = qa + 8;
    int cb = h * DD + (lane & 3) * 2;
    if (qa < SS) {
        size_t mrow = ((size_t)b * SS + qa) * EE;
        #pragma unroll
        for (int nt = 0; nt < 8; nt++) {
            uint32_t hv, lv;
            packhl(o[nt][0] * inv0, o[nt][1] * inv0, hv, lv);
            *(uint32_t*)(g_Oh + mrow + cb + nt * 8) = hv;
            *(uint32_t*)(g_Ol + mrow + cb + nt * 8) = lv;
        }
    }
    if (qb < SS) {
        size_t mrow = ((size_t)b * SS + qb) * EE;
        #pragma unroll
        for (int nt = 0; nt < 8; nt++) {
            uint32_t hv, lv;
            packhl(o[nt][2] * inv1, o[nt][3] * inv1, hv, lv);
            *(uint32_t*)(g_Oh + mrow + cb + nt * 8) = hv;
            *(uint32_t*)(g_Ol + mrow + cb + nt * 8) = lv;
        }
    }
}

// ---------------------------------------------------------------------------
extern "C" void kernel_launch(void* const* d_in, const int* in_sizes, int n_in,
                              void* d_out, int out_size)
{
    (void)in_sizes; (void)n_in; (void)out_size;
    const float* x  = (const float*)d_in[0];
    const float* Wq = (const float*)d_in[1];
    const float* Wk = (const float*)d_in[2];
    const float* Wv = (const float*)d_in[3];
    const float* Wo = (const float*)d_in[4];
    const float* bo = (const float*)d_in[5];
    float* out = (float*)d_out;

    __nv_bfloat16 *pXh, *pXl, *pWh, *pWl, *pUh, *pUl, *pOh, *pOl;
    cudaGetSymbolAddress((void**)&pXh, g_Xh);
    cudaGetSymbolAddress((void**)&pXl, g_Xl);
    cudaGetSymbolAddress((void**)&pWh, g_Wh);
    cudaGetSymbolAddress((void**)&pWl, g_Wl);
    cudaGetSymbolAddress((void**)&pUh, g_Uh);
    cudaGetSymbolAddress((void**)&pUl, g_Ul);
    cudaGetSymbolAddress((void**)&pOh, g_Oh);
    cudaGetSymbolAddress((void**)&pOl, g_Ol);

    cudaFuncSetAttribute(gemm_hmma, cudaFuncAttributeMaxDynamicSharedMemorySize, GSMEM);
    cudaFuncSetAttribute(attn_hmma, cudaFuncAttributeMaxDynamicSharedMemorySize, ATT_SMEM);

    // 1. split inputs / weights to bf16 hi/lo
    split_kernel<<<(unsigned)(((size_t)MPAD * EE) / 1024), 256>>>(
        x, pXh, pXl, (size_t)BSS * EE, (size_t)MPAD * EE);
    convw_kernel<<<dim3(3, HH, EE / 64), 256>>>(Wq, Wk, Wv);
    split_kernel<<<(unsigned)(((size_t)EE * EE) / 1024), 256>>>(
        Wo, pUh, pUl, (size_t)EE * EE, (size_t)EE * EE);

    // 2. fused QKV projection -> bf16 hi/lo Q/K/V
    gemm_hmma<<<dim3(MPAD / TM, NQKV / TN), 256, GSMEM>>>(
        pXh, pXl, pWh, pWl, nullptr, nullptr, 0);

    // 3. flash attention on tensor cores -> bf16 hi/lo O
    attn_hmma<<<dim3(SPAD / 128, HH, BB), 256, ATT_SMEM>>>();

    // 4. output projection
    gemm_hmma<<<dim3(MPAD / TM, EE / TN), 256, GSMEM>>>(
        pOh, pOl, pUh, pUl, out, bo, 1);
}

// round 15
// speedup vs baseline: 4.0802x; 1.3371x over previous
#include <cuda_runtime.h>
#include <cuda_fp16.h>
#include <cstdint>

#define BB  32
#define SS  577
#define EE  1024
#define HH  16
#define DD  64
#define BSS (BB*SS)     // 18464
#define MPAD 18560      // 145*128
#define NQKV 3072
#define SPAD 640        // padded seq (5*128)

// ---------------------------------------------------------------------------
// Device global scratch (allocation-free; statically zero-initialized)
// fp16 2-term scheme: Q and attn-out are hi/lo split; K, V, W, Wo single fp16.
// ---------------------------------------------------------------------------
__device__ __half g_Qh[(size_t)BB*HH*SPAD*DD];
__device__ __half g_Ql[(size_t)BB*HH*SPAD*DD];
__device__ __half g_Kh[(size_t)BB*HH*SPAD*DD];
__device__ __half g_Vh[(size_t)BB*HH*SPAD*DD];

__device__ __half g_Xh[(size_t)MPAD*EE];
__device__ __half g_Xl[(size_t)MPAD*EE];
__device__ __half g_Wh[(size_t)NQKV*EE];      // QKV weights, single fp16
__device__ __half g_Uh[(size_t)EE*EE];        // Wo, single fp16
__device__ __half g_Oh[(size_t)MPAD*EE];      // attn out hi (proj A), padding 0
__device__ __half g_Ol[(size_t)MPAD*EE];      // attn out lo

// ---------------------------------------------------------------------------
// Helpers (sm_80-baseline PTX only — harness compiles compute_103, no tcgen05)
// ---------------------------------------------------------------------------
__device__ __forceinline__ uint32_t smem_u32(const void* p) {
    uint32_t a;
    asm("{ .reg .u64 t; cvta.to.shared.u64 t, %1; cvt.u32.u64 %0, t; }"
        : "=r"(a) : "l"(p));
    return a;
}

__device__ __forceinline__ uint32_t swz(uint32_t off) {    // 128B-row swizzle
    return off ^ ((off >> 3) & 0x70);
}
__device__ __forceinline__ uint32_t swz64(uint32_t off) {  // 64B-row swizzle
    return off ^ ((off >> 3) & 0x30);
}

#define CP16(dst, src) \
    asm volatile("cp.async.cg.shared.global [%0], [%1], 16;" \
                 :: "r"(dst), "l"(src) : "memory")

#define LDSM4(r0, r1, r2, r3, addr) \
    asm volatile("ldmatrix.sync.aligned.m8n8.x4.shared.b16 {%0,%1,%2,%3}, [%4];" \
                 : "=r"(r0), "=r"(r1), "=r"(r2), "=r"(r3) : "r"(addr))

#define LDSM4T(r0, r1, r2, r3, addr) \
    asm volatile("ldmatrix.sync.aligned.m8n8.x4.trans.shared.b16 {%0,%1,%2,%3}, [%4];" \
                 : "=r"(r0), "=r"(r1), "=r"(r2), "=r"(r3) : "r"(addr))

#define MMA16816(d, a, b) \
    asm volatile("mma.sync.aligned.m16n8k16.row.col.f32.f16.f16.f32 " \
                 "{%0,%1,%2,%3}, {%4,%5,%6,%7}, {%8,%9}, {%0,%1,%2,%3};" \
                 : "+f"((d)[0]), "+f"((d)[1]), "+f"((d)[2]), "+f"((d)[3]) \
                 : "r"((a)[0]), "r"((a)[1]), "r"((a)[2]), "r"((a)[3]), \
                   "r"((b)[0]), "r"((b)[1]))

// pack two floats into fp16x2 hi + fp16x2 lo (lo = residual)
__device__ __forceinline__ void packhl(float a, float b, uint32_t& hi, uint32_t& lo) {
    __half ha = __float2half_rn(a), hb = __float2half_rn(b);
    __half la = __float2half_rn(a - __half2float(ha));
    __half lb = __float2half_rn(b - __half2float(hb));
    __half2 H = __halves2half2(ha, hb);
    __half2 L = __halves2half2(la, lb);
    hi = *(uint32_t*)&H;
    lo = *(uint32_t*)&L;
}
__device__ __forceinline__ uint32_t pack2h(float a, float b) {
    __half2 H = __halves2half2(__float2half_rn(a), __float2half_rn(b));
    return *(uint32_t*)&H;
}

// ---------------------------------------------------------------------------
// fp32 -> fp16 hi/lo split (zero pad beyond n_valid)    [x only]
// ---------------------------------------------------------------------------
__global__ void split_kernel(const float* __restrict__ src,
                             __half* __restrict__ hd, __half* __restrict__ ld,
                             size_t n_valid, size_t n_total)
{
    size_t i = ((size_t)blockIdx.x * 256 + threadIdx.x) * 4;
    if (i >= n_total) return;
    float4 v = make_float4(0.f, 0.f, 0.f, 0.f);
    if (i < n_valid) v = *(const float4*)(src + i);
    uint32_t h01, l01, h23, l23;
    packhl(v.x, v.y, h01, l01);
    packhl(v.z, v.w, h23, l23);
    ((uint32_t*)hd)[(i >> 1) + 0] = h01;
    ((uint32_t*)hd)[(i >> 1) + 1] = h23;
    ((uint32_t*)ld)[(i >> 1) + 0] = l01;
    ((uint32_t*)ld)[(i >> 1) + 1] = l23;
}

// fp32 -> single fp16 convert   [Wo]
__global__ void conv1_kernel(const float* __restrict__ src, __half* __restrict__ dst,
                             size_t n)
{
    size_t i = ((size_t)blockIdx.x * 256 + threadIdx.x) * 4;
    if (i >= n) return;
    float4 v = *(const float4*)(src + i);
    ((uint32_t*)dst)[(i >> 1) + 0] = pack2h(v.x, v.y);
    ((uint32_t*)dst)[(i >> 1) + 1] = pack2h(v.z, v.w);
}

// QKV weights [H][E][D] x3 -> B rows n = mat*1024 + h*64 + d, cols k = e
// Coalesced both sides via 64x64 smem transpose tile; single fp16 out.
__global__ void convw_kernel(const float* __restrict__ Wq,
                             const float* __restrict__ Wk,
                             const float* __restrict__ Wv)
{
    __shared__ float t[64][65];
    const int mat = blockIdx.x, h = blockIdx.y, e0 = blockIdx.z * 64;
    const float* W = (mat == 0) ? Wq : (mat == 1) ? Wk : Wv;
    const int tid = threadIdx.x;

    for (int i = tid; i < 64 * 64; i += 256) {
        int e = i >> 6, d = i & 63;
        t[d][e] = W[((size_t)h * EE + e0 + e) * DD + d];
    }
    __syncthreads();

    for (int i = tid; i < 64 * 64; i += 256) {
        int d = i >> 6, e = i & 63;
        size_t off = (size_t)(mat * 1024 + h * 64 + d) * EE + e0 + e;
        g_Wh[off] = __float2half_rn(t[d][e]);
    }
}

// ---------------------------------------------------------------------------
// 2-term fp16 HMMA GEMM:  C[M,N] = (Ah+Al)[M,K] * Bh[N,K]^T
//   128x128 block, 8 warps (32m x 64n each), KC=32 chunks, 64B rows (SW64),
//   2-stage cp.async (24KB/stage), 2 CTAs/SM. Term-major MMA order.
//   mode 0: scatter -> Qh/Ql (mat 0), Kh (mat 1), Vh (mat 2), SPAD stride
//   mode 1: outp = C + bias (fp32)
// ---------------------------------------------------------------------------
#define TM 128
#define TN 128
#define KC 32
#define TILEB 8192                     // 128 rows x 32 fp16 = 64B rows
#define STAGEB (3*TILEB)               // Ah, Al, Bh = 24KB
#define GSMEM (2*STAGEB)               // 48KB

__device__ __forceinline__ void issue_stage(
    uint32_t sbase,
    const __half* __restrict__ Ah_, const __half* __restrict__ Al_,
    const __half* __restrict__ Bh_,
    int m0, int n0, int kt, int tid)
{
    #pragma unroll
    for (int i = 0; i < 2; i++) {
        int f = tid + 256 * i;          // 512 granules per matrix
        int row = f >> 2, c = f & 3;
        uint32_t doff = swz64((uint32_t)(row * 64 + c * 16));
        size_t aoff = (size_t)(m0 + row) * EE + kt * KC + c * 8;
        size_t boff = (size_t)(n0 + row) * EE + kt * KC + c * 8;
        CP16(sbase + doff,              (const char*)(Ah_ + aoff));
        CP16(sbase + TILEB + doff,      (const char*)(Al_ + aoff));
        CP16(sbase + 2 * TILEB + doff,  (const char*)(Bh_ + boff));
    }
}

__device__ __forceinline__ void compute_chunk(
    uint32_t sbase, int wm, int wn, int lane, float (&acc)[2][8][4])
{
    const uint32_t aH = sbase, aL = sbase + TILEB;
    const uint32_t bH = sbase + 2 * TILEB;
    #pragma unroll
    for (int ks = 0; ks < 2; ks++) {
        uint32_t ah[2][4], al[2][4];
        #pragma unroll
        for (int mt = 0; mt < 2; mt++) {
            uint32_t off = swz64((uint32_t)((wm + mt * 16 + (lane & 15)) * 64
                                          + ks * 32 + (lane >> 4) * 16));
            LDSM4(ah[mt][0], ah[mt][1], ah[mt][2], ah[mt][3], aH + off);
            LDSM4(al[mt][0], al[mt][1], al[mt][2], al[mt][3], aL + off);
        }
        #pragma unroll
        for (int p = 0; p < 4; p++) {
            uint32_t bh[4];
            uint32_t off = swz64((uint32_t)((wn + p * 16 + (lane & 7) + ((lane >> 4) & 1) * 8) * 64
                                          + ks * 32 + ((lane >> 3) & 1) * 16));
            LDSM4(bh[0], bh[1], bh[2], bh[3], bH + off);
            // term-major, same-acc reuse distance 4
            MMA16816(acc[0][2*p],   ah[0], bh);
            MMA16816(acc[1][2*p],   ah[1], bh);
            MMA16816(acc[0][2*p+1], ah[0], bh + 2);
            MMA16816(acc[1][2*p+1], ah[1], bh + 2);

            MMA16816(acc[0][2*p],   al[0], bh);
            MMA16816(acc[1][2*p],   al[1], bh);
            MMA16816(acc[0][2*p+1], al[0], bh + 2);
            MMA16816(acc[1][2*p+1], al[1], bh + 2);
        }
    }
}

__global__ __launch_bounds__(256, 2)
void gemm_hmma(const __half* __restrict__ Ah, const __half* __restrict__ Al,
               const __half* __restrict__ Bh,
               float* __restrict__ outp, const float* __restrict__ bias, int mode)
{
    extern __shared__ __align__(1024) char smem[];
    const uint32_t sb = smem_u32(smem);
    const int tid = threadIdx.x, lane = tid & 31, wid = tid >> 5;
    const int m0 = blockIdx.x * TM, n0 = blockIdx.y * TN;
    const int wm = (wid & 3) * 32, wn = (wid >> 2) * 64;

    float acc[2][8][4];
    #pragma unroll
    for (int mt = 0; mt < 2; mt++)
        #pragma unroll
        for (int nt = 0; nt < 8; nt++)
            #pragma unroll
            for (int r = 0; r < 4; r++) acc[mt][nt][r] = 0.f;

    const int NK = EE / KC;   // 32
    issue_stage(sb, Ah, Al, Bh, m0, n0, 0, tid);
    asm volatile("cp.async.commit_group;" ::: "memory");

    int buf = 0;
    for (int kt = 0; kt < NK; kt++) {
        if (kt + 1 < NK) {
            issue_stage(sb + (buf ^ 1) * STAGEB, Ah, Al, Bh, m0, n0, kt + 1, tid);
            asm volatile("cp.async.commit_group;" ::: "memory");
            asm volatile("cp.async.wait_group 1;" ::: "memory");
        } else {
            asm volatile("cp.async.wait_group 0;" ::: "memory");
        }
        __syncthreads();
        compute_chunk(sb + buf * STAGEB, wm, wn, lane, acc);
        __syncthreads();
        buf ^= 1;
    }

    #pragma unroll
    for (int mt = 0; mt < 2; mt++) {
        #pragma unroll
        for (int half = 0; half < 2; half++) {
            int m = m0 + wm + mt * 16 + (lane >> 2) + half * 8;
            if (m >= BSS) continue;
            if (mode == 0) {
                int bb = m / SS, ss = m - bb * SS;
                #pragma unroll
                for (int nt = 0; nt < 8; nt++) {
                    int col = n0 + wn + nt * 8 + (lane & 3) * 2;
                    int mat = col >> 10, hh = (col >> 6) & 15, dd = col & 63;
                    size_t off = (((size_t)bb * HH + hh) * SPAD + ss) * DD + dd;
                    float v0 = acc[mt][nt][half * 2 + 0];
                    float v1 = acc[mt][nt][half * 2 + 1];
                    if (mat == 0) {
                        uint32_t hv, lv;
                        packhl(v0, v1, hv, lv);
                        *(uint32_t*)(g_Qh + off) = hv;
                        *(uint32_t*)(g_Ql + off) = lv;
                    } else if (mat == 1) {
                        *(uint32_t*)(g_Kh + off) = pack2h(v0, v1);
                    } else {
                        *(uint32_t*)(g_Vh + off) = pack2h(v0, v1);
                    }
                }
            } else {
                float* op = outp + (size_t)m * EE;
                #pragma unroll
                for (int nt = 0; nt < 8; nt++) {
                    int col = n0 + wn + nt * 8 + (lane & 3) * 2;
                    op[col]     = acc[mt][nt][half * 2 + 0] + __ldg(bias + col);
                    op[col + 1] = acc[mt][nt][half * 2 + 1] + __ldg(bias + col + 1);
                }
            }
        }
    }
}

// ---------------------------------------------------------------------------
// 2-term fp16 HMMA flash attention (FA2-style).
//   QK: (Qh+Ql)·Kh   PV: (Ph+Pl)·Vh — K and V single fp16.
//   KV stage = Kh(8K)+Vh(8K) = 16KB, double buffered (32KB total).
// ---------------------------------------------------------------------------
#define KVSTG 16384
#define ATT_SMEM (2*KVSTG)
#define NKT (SPAD/64)    // 10

__device__ __forceinline__ void attn_issue(uint32_t sbase, size_t bhq, int j0, int tid)
{
    #pragma unroll
    for (int i = 0; i < 2; i++) {
        int f = tid + 256 * i;          // 512 granules per matrix
        int row = f >> 3, c = f & 7;
        uint32_t doff = swz((uint32_t)(row * 128 + c * 16));
        size_t go = bhq + (size_t)(j0 + row) * DD + c * 8;
        CP16(sbase +         doff, (const char*)(g_Kh + go));
        CP16(sbase + 8192u + doff, (const char*)(g_Vh + go));
    }
}

__global__ __launch_bounds__(256)
void attn_hmma()
{
    extern __shared__ __align__(1024) char smem[];
    const uint32_t sb = smem_u32(smem);
    const int tid = threadIdx.x, lane = tid & 31, wid = tid >> 5;
    const int b = blockIdx.z, h = blockIdx.y, q0 = blockIdx.x * 128;
    const int wm = wid * 16;
    const size_t bh = ((size_t)b * HH + h) * SPAD * DD;

    // stage Q hi/lo through the 32KB (16KB each), build frags, then release
    #pragma unroll
    for (int i = 0; i < 4; i++) {
        int f = tid + 256 * i;          // 1024 granules per matrix
        int row = f >> 3, c = f & 7;
        uint32_t doff = swz((uint32_t)(row * 128 + c * 16));
        size_t go = bh + (size_t)(q0 + row) * DD + c * 8;
        CP16(sb + doff,          (const char*)(g_Qh + go));
        CP16(sb + 16384u + doff, (const char*)(g_Ql + go));
    }
    asm volatile("cp.async.commit_group;" ::: "memory");
    asm volatile("cp.async.wait_group 0;" ::: "memory");
    __syncthreads();

    uint32_t qh[4][4], ql[4][4];
    #pragma unroll
    for (int ks = 0; ks < 4; ks++) {
        uint32_t off = swz((uint32_t)((wm + (lane & 15)) * 128
                                    + (ks * 16 + (lane >> 4) * 8) * 2));
        LDSM4(qh[ks][0], qh[ks][1], qh[ks][2], qh[ks][3], sb + off);
        LDSM4(ql[ks][0], ql[ks][1], ql[ks][2], ql[ks][3], sb + 16384u + off);
    }
    __syncthreads();

    float o[8][4];
    #pragma unroll
    for (int nt = 0; nt < 8; nt++)
        #pragma unroll
        for (int r = 0; r < 4; r++) o[nt][r] = 0.f;
    float m0r = -1e30f, m1r = -1e30f, l0r = 0.f, l1r = 0.f;

    attn_issue(sb, bh, 0, tid);
    asm volatile("cp.async.commit_group;" ::: "memory");
    attn_issue(sb + KVSTG, bh, 64, tid);
    asm volatile("cp.async.commit_group;" ::: "memory");

    for (int t = 0; t < NKT; t++) {
        const uint32_t st = sb + (t & 1) * KVSTG;
        const int j0 = t * 64;
        if (t == NKT - 1) asm volatile("cp.async.wait_group 0;" ::: "memory");
        else              asm volatile("cp.async.wait_group 1;" ::: "memory");
        __syncthreads();

        float s[8][4];
        #pragma unroll
        for (int nt = 0; nt < 8; nt++)
            #pragma unroll
            for (int r = 0; r < 4; r++) s[nt][r] = 0.f;

        #pragma unroll
        for (int ks = 0; ks < 4; ks++) {
            uint32_t kh[8][2];
            #pragma unroll
            for (int p = 0; p < 4; p++) {
                uint32_t off = swz((uint32_t)((p * 16 + (lane & 7) + ((lane >> 4) & 1) * 8) * 128
                                            + (ks * 16 + ((lane >> 3) & 1) * 8) * 2));
                LDSM4(kh[2*p][0], kh[2*p][1], kh[2*p+1][0], kh[2*p+1][1], st + off);
            }
            #pragma unroll
            for (int nt = 0; nt < 8; nt++) MMA16816(s[nt], qh[ks], kh[nt]);
            #pragma unroll
            for (int nt = 0; nt < 8; nt++) MMA16816(s[nt], ql[ks], kh[nt]);
        }

        #pragma unroll
        for (int nt = 0; nt < 8; nt++)
            #pragma unroll
            for (int r = 0; r < 4; r++) s[nt][r] *= 0.125f;
        if (j0 + 64 > SS) {
            #pragma unroll
            for (int nt = 0; nt < 8; nt++) {
                int k0 = j0 + nt * 8 + (lane & 3) * 2;
                if (k0 >= SS)     { s[nt][0] = -1e30f; s[nt][2] = -1e30f; }
                if (k0 + 1 >= SS) { s[nt][1] = -1e30f; s[nt][3] = -1e30f; }
            }
        }

        float mx0 = -1e30f, mx1 = -1e30f;
        #pragma unroll
        for (int nt = 0; nt < 8; nt++) {
            mx0 = fmaxf(mx0, fmaxf(s[nt][0], s[nt][1]));
            mx1 = fmaxf(mx1, fmaxf(s[nt][2], s[nt][3]));
        }
        mx0 = fmaxf(mx0, __shfl_xor_sync(0xffffffffu, mx0, 1));
        mx0 = fmaxf(mx0, __shfl_xor_sync(0xffffffffu, mx0, 2));
        mx1 = fmaxf(mx1, __shfl_xor_sync(0xffffffffu, mx1, 1));
        mx1 = fmaxf(mx1, __shfl_xor_sync(0xffffffffu, mx1, 2));
        float nm0 = fmaxf(m0r, mx0), nm1 = fmaxf(m1r, mx1);
        float c0 = __expf(m0r - nm0), c1 = __expf(m1r - nm1);
        m0r = nm0; m1r = nm1;
        float sum0 = 0.f, sum1 = 0.f;
        #pragma unroll
        for (int nt = 0; nt < 8; nt++) {
            s[nt][0] = __expf(s[nt][0] - nm0); sum0 += s[nt][0];
            s[nt][1] = __expf(s[nt][1] - nm0); sum0 += s[nt][1];
            s[nt][2] = __expf(s[nt][2] - nm1); sum1 += s[nt][2];
            s[nt][3] = __expf(s[nt][3] - nm1); sum1 += s[nt][3];
        }
        sum0 += __shfl_xor_sync(0xffffffffu, sum0, 1);
        sum0 += __shfl_xor_sync(0xffffffffu, sum0, 2);
        sum1 += __shfl_xor_sync(0xffffffffu, sum1, 1);
        sum1 += __shfl_xor_sync(0xffffffffu, sum1, 2);
        l0r = l0r * c0 + sum0;
        l1r = l1r * c1 + sum1;
        #pragma unroll
        for (int nt = 0; nt < 8; nt++) {
            o[nt][0] *= c0; o[nt][1] *= c0;
            o[nt][2] *= c1; o[nt][3] *= c1;
        }

        #pragma unroll
        for (int ks2 = 0; ks2 < 4; ks2++) {
            uint32_t ph[4], pl[4];
            packhl(s[2*ks2][0],   s[2*ks2][1],   ph[0], pl[0]);
            packhl(s[2*ks2][2],   s[2*ks2][3],   ph[1], pl[1]);
            packhl(s[2*ks2+1][0], s[2*ks2+1][1], ph[2], pl[2]);
            packhl(s[2*ks2+1][2], s[2*ks2+1][3], ph[3], pl[3]);

            uint32_t vh[8][2];
            #pragma unroll
            for (int p = 0; p < 4; p++) {
                uint32_t off = swz((uint32_t)((ks2 * 16 + ((lane >> 3) & 1) * 8 + (lane & 7)) * 128
                                            + (p * 16 + ((lane >> 4) & 1) * 8) * 2));
                LDSM4T(vh[2*p][0], vh[2*p][1], vh[2*p+1][0], vh[2*p+1][1], st + 8192u + off);
            }
            #pragma unroll
            for (int nt = 0; nt < 8; nt++) MMA16816(o[nt], ph, vh[nt]);
            #pragma unroll
            for (int nt = 0; nt < 8; nt++) MMA16816(o[nt], pl, vh[nt]);
        }
        __syncthreads();
        if (t + 2 < NKT) {
            attn_issue(st, bh, (t + 2) * 64, tid);
            asm volatile("cp.async.commit_group;" ::: "memory");
        }
    }

    // epilogue: O/l -> fp16 hi/lo in proj-A layout [b*SS+s][h*64+d]
    float inv0 = 1.f / l0r, inv1 = 1.f / l1r;
    int qa = q0 + wm + (lane >> 2);
    int qb = qa + 8;
    int cb = h * DD + (lane & 3) * 2;
    if (qa < SS) {
        size_t mrow = ((size_t)b * SS + qa) * EE;
        #pragma unroll
        for (int nt = 0; nt < 8; nt++) {
            uint32_t hv, lv;
            packhl(o[nt][0] * inv0, o[nt][1] * inv0, hv, lv);
            *(uint32_t*)(g_Oh + mrow + cb + nt * 8) = hv;
            *(uint32_t*)(g_Ol + mrow + cb + nt * 8) = lv;
        }
    }
    if (qb < SS) {
        size_t mrow = ((size_t)b * SS + qb) * EE;
        #pragma unroll
        for (int nt = 0; nt < 8; nt++) {
            uint32_t hv, lv;
            packhl(o[nt][2] * inv1, o[nt][3] * inv1, hv, lv);
            *(uint32_t*)(g_Oh + mrow + cb + nt * 8) = hv;
            *(uint32_t*)(g_Ol + mrow + cb + nt * 8) = lv;
        }
    }
}

// ---------------------------------------------------------------------------
extern "C" void kernel_launch(void* const* d_in, const int* in_sizes, int n_in,
                              void* d_out, int out_size)
{
    (void)in_sizes; (void)n_in; (void)out_size;
    const float* x  = (const float*)d_in[0];
    const float* Wq = (const float*)d_in[1];
    const float* Wk = (const float*)d_in[2];
    const float* Wv = (const float*)d_in[3];
    const float* Wo = (const float*)d_in[4];
    const float* bo = (const float*)d_in[5];
    float* out = (float*)d_out;

    __half *pXh, *pXl, *pWh, *pUh, *pOh, *pOl;
    cudaGetSymbolAddress((void**)&pXh, g_Xh);
    cudaGetSymbolAddress((void**)&pXl, g_Xl);
    cudaGetSymbolAddress((void**)&pWh, g_Wh);
    cudaGetSymbolAddress((void**)&pUh, g_Uh);
    cudaGetSymbolAddress((void**)&pOh, g_Oh);
    cudaGetSymbolAddress((void**)&pOl, g_Ol);

    cudaFuncSetAttribute(gemm_hmma, cudaFuncAttributeMaxDynamicSharedMemorySize, GSMEM);
    cudaFuncSetAttribute(attn_hmma, cudaFuncAttributeMaxDynamicSharedMemorySize, ATT_SMEM);

    // 1. converts: x -> fp16 hi/lo; W -> fp16; Wo -> fp16
    split_kernel<<<(unsigned)(((size_t)MPAD * EE) / 1024), 256>>>(
        x, pXh, pXl, (size_t)BSS * EE, (size_t)MPAD * EE);
    convw_kernel<<<dim3(3, HH, EE / 64), 256>>>(Wq, Wk, Wv);
    conv1_kernel<<<(unsigned)(((size_t)EE * EE) / 1024), 256>>>(
        Wo, pUh, (size_t)EE * EE);

    // 2. fused QKV projection -> Qh/Ql, Kh, Vh
    gemm_hmma<<<dim3(MPAD / TM, NQKV / TN), 256, GSMEM>>>(
        pXh, pXl, pWh, nullptr, nullptr, 0);

    // 3. flash attention -> Oh/Ol
    attn_hmma<<<dim3(SPAD / 128, HH, BB), 256, ATT_SMEM>>>();

    // 4. output projection
    gemm_hmma<<<dim3(MPAD / TM, EE / TN), 256, GSMEM>>>(
        pOh, pOl, pUh, out, bo, 1);
}

// round 16
// speedup vs baseline: 4.3454x; 1.0650x over previous
#include <cuda_runtime.h>
#include <cuda_fp16.h>
#include <cstdint>

#define BB  32
#define SS  577
#define EE  1024
#define HH  16
#define DD  64
#define BSS (BB*SS)     // 18464
#define MPAD 18560      // 145*128
#define NQKV 3072
#define SPAD 640        // padded seq (5*128)

// ---------------------------------------------------------------------------
// Device global scratch (allocation-free; statically zero-initialized)
// fp16 2-term scheme: Q and attn-out hi/lo split; K, V, W, Wo single fp16.
// ---------------------------------------------------------------------------
__device__ __half g_Qh[(size_t)BB*HH*SPAD*DD];
__device__ __half g_Ql[(size_t)BB*HH*SPAD*DD];
__device__ __half g_Kh[(size_t)BB*HH*SPAD*DD];
__device__ __half g_Vh[(size_t)BB*HH*SPAD*DD];

__device__ __half g_Xh[(size_t)MPAD*EE];
__device__ __half g_Xl[(size_t)MPAD*EE];
__device__ __half g_Wh[(size_t)NQKV*EE];      // QKV weights, single fp16
__device__ __half g_Uh[(size_t)EE*EE];        // Wo, single fp16
__device__ __half g_Oh[(size_t)MPAD*EE];      // attn out hi (proj A), padding 0
__device__ __half g_Ol[(size_t)MPAD*EE];      // attn out lo

// ---------------------------------------------------------------------------
// Helpers (sm_80-baseline PTX only — harness compiles compute_103, no tcgen05)
// ---------------------------------------------------------------------------
__device__ __forceinline__ uint32_t smem_u32(const void* p) {
    uint32_t a;
    asm("{ .reg .u64 t; cvta.to.shared.u64 t, %1; cvt.u32.u64 %0, t; }"
        : "=r"(a) : "l"(p));
    return a;
}

__device__ __forceinline__ uint32_t swz(uint32_t off) {    // 128B-row swizzle
    return off ^ ((off >> 3) & 0x70);
}
__device__ __forceinline__ uint32_t swz64(uint32_t off) {  // 64B-row swizzle
    return off ^ ((off >> 3) & 0x30);
}

#define CP16(dst, src) \
    asm volatile("cp.async.cg.shared.global [%0], [%1], 16;" \
                 :: "r"(dst), "l"(src) : "memory")

#define LDSM4(r0, r1, r2, r3, addr) \
    asm volatile("ldmatrix.sync.aligned.m8n8.x4.shared.b16 {%0,%1,%2,%3}, [%4];" \
                 : "=r"(r0), "=r"(r1), "=r"(r2), "=r"(r3) : "r"(addr))

#define LDSM4T(r0, r1, r2, r3, addr) \
    asm volatile("ldmatrix.sync.aligned.m8n8.x4.trans.shared.b16 {%0,%1,%2,%3}, [%4];" \
                 : "=r"(r0), "=r"(r1), "=r"(r2), "=r"(r3) : "r"(addr))

#define MMA16816(d, a, b) \
    asm volatile("mma.sync.aligned.m16n8k16.row.col.f32.f16.f16.f32 " \
                 "{%0,%1,%2,%3}, {%4,%5,%6,%7}, {%8,%9}, {%0,%1,%2,%3};" \
                 : "+f"((d)[0]), "+f"((d)[1]), "+f"((d)[2]), "+f"((d)[3]) \
                 : "r"((a)[0]), "r"((a)[1]), "r"((a)[2]), "r"((a)[3]), \
                   "r"((b)[0]), "r"((b)[1]))

// pack two floats into fp16x2 hi + fp16x2 lo (lo = residual)
__device__ __forceinline__ void packhl(float a, float b, uint32_t& hi, uint32_t& lo) {
    __half ha = __float2half_rn(a), hb = __float2half_rn(b);
    __half la = __float2half_rn(a - __half2float(ha));
    __half lb = __float2half_rn(b - __half2float(hb));
    __half2 H = __halves2half2(ha, hb);
    __half2 L = __halves2half2(la, lb);
    hi = *(uint32_t*)&H;
    lo = *(uint32_t*)&L;
}
__device__ __forceinline__ uint32_t pack2h(float a, float b) {
    __half2 H = __halves2half2(__float2half_rn(a), __float2half_rn(b));
    return *(uint32_t*)&H;
}

// ---------------------------------------------------------------------------
// fp32 -> fp16 hi/lo split (zero pad beyond n_valid)    [x only]
// ---------------------------------------------------------------------------
__global__ void split_kernel(const float* __restrict__ src,
                             __half* __restrict__ hd, __half* __restrict__ ld,
                             size_t n_valid, size_t n_total)
{
    size_t i = ((size_t)blockIdx.x * 256 + threadIdx.x) * 4;
    if (i >= n_total) return;
    float4 v = make_float4(0.f, 0.f, 0.f, 0.f);
    if (i < n_valid) v = *(const float4*)(src + i);
    uint32_t h01, l01, h23, l23;
    packhl(v.x, v.y, h01, l01);
    packhl(v.z, v.w, h23, l23);
    ((uint32_t*)hd)[(i >> 1) + 0] = h01;
    ((uint32_t*)hd)[(i >> 1) + 1] = h23;
    ((uint32_t*)ld)[(i >> 1) + 0] = l01;
    ((uint32_t*)ld)[(i >> 1) + 1] = l23;
}

// fp32 -> single fp16 convert   [Wo]
__global__ void conv1_kernel(const float* __restrict__ src, __half* __restrict__ dst,
                             size_t n)
{
    size_t i = ((size_t)blockIdx.x * 256 + threadIdx.x) * 4;
    if (i >= n) return;
    float4 v = *(const float4*)(src + i);
    ((uint32_t*)dst)[(i >> 1) + 0] = pack2h(v.x, v.y);
    ((uint32_t*)dst)[(i >> 1) + 1] = pack2h(v.z, v.w);
}

// QKV weights [H][E][D] x3 -> B rows n = mat*1024 + h*64 + d, cols k = e
__global__ void convw_kernel(const float* __restrict__ Wq,
                             const float* __restrict__ Wk,
                             const float* __restrict__ Wv)
{
    __shared__ float t[64][65];
    const int mat = blockIdx.x, h = blockIdx.y, e0 = blockIdx.z * 64;
    const float* W = (mat == 0) ? Wq : (mat == 1) ? Wk : Wv;
    const int tid = threadIdx.x;

    for (int i = tid; i < 64 * 64; i += 256) {
        int e = i >> 6, d = i & 63;
        t[d][e] = W[((size_t)h * EE + e0 + e) * DD + d];
    }
    __syncthreads();

    for (int i = tid; i < 64 * 64; i += 256) {
        int d = i >> 6, e = i & 63;
        size_t off = (size_t)(mat * 1024 + h * 64 + d) * EE + e0 + e;
        g_Wh[off] = __float2half_rn(t[d][e]);
    }
}

// ---------------------------------------------------------------------------
// 2-term fp16 HMMA GEMM with PRECISION-ADAPTIVE N-blocks:
//   C[M,N] = (Ah[+Al])[M,K] * Bh[N,K]^T
//   Blocks producing K/V (mode 0, n0>=1024) drop the Al term entirely —
//   their outputs are rounded to single fp16 anyway, so the correction is
//   below the output rounding floor. Q blocks and proj keep 2 terms.
// ---------------------------------------------------------------------------
#define TM 128
#define TN 128
#define KC 32
#define TILEB 8192                     // 128 rows x 32 fp16 = 64B rows
#define STAGEB (3*TILEB)               // Ah, Al, Bh = 24KB
#define GSMEM (2*STAGEB)               // 48KB

__device__ __forceinline__ void issue_stage(
    uint32_t sbase,
    const __half* __restrict__ Ah_, const __half* __restrict__ Al_,
    const __half* __restrict__ Bh_,
    int m0, int n0, int kt, int tid, int twoTerm)
{
    #pragma unroll
    for (int i = 0; i < 2; i++) {
        int f = tid + 256 * i;          // 512 granules per matrix
        int row = f >> 2, c = f & 3;
        uint32_t doff = swz64((uint32_t)(row * 64 + c * 16));
        size_t aoff = (size_t)(m0 + row) * EE + kt * KC + c * 8;
        size_t boff = (size_t)(n0 + row) * EE + kt * KC + c * 8;
        CP16(sbase + doff,              (const char*)(Ah_ + aoff));
        if (twoTerm)
            CP16(sbase + TILEB + doff,  (const char*)(Al_ + aoff));
        CP16(sbase + 2 * TILEB + doff,  (const char*)(Bh_ + boff));
    }
}

__device__ __forceinline__ void compute_chunk(
    uint32_t sbase, int wm, int wn, int lane, float (&acc)[2][8][4], int twoTerm)
{
    const uint32_t aH = sbase, aL = sbase + TILEB;
    const uint32_t bH = sbase + 2 * TILEB;
    #pragma unroll
    for (int ks = 0; ks < 2; ks++) {
        uint32_t ah[2][4], al[2][4];
        #pragma unroll
        for (int mt = 0; mt < 2; mt++) {
            uint32_t off = swz64((uint32_t)((wm + mt * 16 + (lane & 15)) * 64
                                          + ks * 32 + (lane >> 4) * 16));
            LDSM4(ah[mt][0], ah[mt][1], ah[mt][2], ah[mt][3], aH + off);
            if (twoTerm)
                LDSM4(al[mt][0], al[mt][1], al[mt][2], al[mt][3], aL + off);
        }
        #pragma unroll
        for (int p = 0; p < 4; p++) {
            uint32_t bh[4];
            uint32_t off = swz64((uint32_t)((wn + p * 16 + (lane & 7) + ((lane >> 4) & 1) * 8) * 64
                                          + ks * 32 + ((lane >> 3) & 1) * 16));
            LDSM4(bh[0], bh[1], bh[2], bh[3], bH + off);
            // term-major, same-acc reuse distance 4
            MMA16816(acc[0][2*p],   ah[0], bh);
            MMA16816(acc[1][2*p],   ah[1], bh);
            MMA16816(acc[0][2*p+1], ah[0], bh + 2);
            MMA16816(acc[1][2*p+1], ah[1], bh + 2);
            if (twoTerm) {
                MMA16816(acc[0][2*p],   al[0], bh);
                MMA16816(acc[1][2*p],   al[1], bh);
                MMA16816(acc[0][2*p+1], al[0], bh + 2);
                MMA16816(acc[1][2*p+1], al[1], bh + 2);
            }
        }
    }
}

__global__ __launch_bounds__(256, 2)
void gemm_hmma(const __half* __restrict__ Ah, const __half* __restrict__ Al,
               const __half* __restrict__ Bh,
               float* __restrict__ outp, const float* __restrict__ bias, int mode)
{
    extern __shared__ __align__(1024) char smem[];
    const uint32_t sb = smem_u32(smem);
    const int tid = threadIdx.x, lane = tid & 31, wid = tid >> 5;
    const int m0 = blockIdx.x * TM, n0 = blockIdx.y * TN;
    const int wm = (wid & 3) * 32, wn = (wid >> 2) * 64;
    // K/V output blocks skip the Al refinement (below their fp16 output rounding)
    const int twoTerm = (mode == 1) || (n0 < 1024);

    float acc[2][8][4];
    #pragma unroll
    for (int mt = 0; mt < 2; mt++)
        #pragma unroll
        for (int nt = 0; nt < 8; nt++)
            #pragma unroll
            for (int r = 0; r < 4; r++) acc[mt][nt][r] = 0.f;

    const int NK = EE / KC;   // 32
    issue_stage(sb, Ah, Al, Bh, m0, n0, 0, tid, twoTerm);
    asm volatile("cp.async.commit_group;" ::: "memory");

    int buf = 0;
    for (int kt = 0; kt < NK; kt++) {
        if (kt + 1 < NK) {
            issue_stage(sb + (buf ^ 1) * STAGEB, Ah, Al, Bh, m0, n0, kt + 1, tid, twoTerm);
            asm volatile("cp.async.commit_group;" ::: "memory");
            asm volatile("cp.async.wait_group 1;" ::: "memory");
        } else {
            asm volatile("cp.async.wait_group 0;" ::: "memory");
        }
        __syncthreads();
        compute_chunk(sb + buf * STAGEB, wm, wn, lane, acc, twoTerm);
        __syncthreads();
        buf ^= 1;
    }

    #pragma unroll
    for (int mt = 0; mt < 2; mt++) {
        #pragma unroll
        for (int half = 0; half < 2; half++) {
            int m = m0 + wm + mt * 16 + (lane >> 2) + half * 8;
            if (m >= BSS) continue;
            if (mode == 0) {
                int bb = m / SS, ss = m - bb * SS;
                #pragma unroll
                for (int nt = 0; nt < 8; nt++) {
                    int col = n0 + wn + nt * 8 + (lane & 3) * 2;
                    int mat = col >> 10, hh = (col >> 6) & 15, dd = col & 63;
                    size_t off = (((size_t)bb * HH + hh) * SPAD + ss) * DD + dd;
                    float v0 = acc[mt][nt][half * 2 + 0];
                    float v1 = acc[mt][nt][half * 2 + 1];
                    if (mat == 0) {
                        uint32_t hv, lv;
                        packhl(v0, v1, hv, lv);
                        *(uint32_t*)(g_Qh + off) = hv;
                        *(uint32_t*)(g_Ql + off) = lv;
                    } else if (mat == 1) {
                        *(uint32_t*)(g_Kh + off) = pack2h(v0, v1);
                    } else {
                        *(uint32_t*)(g_Vh + off) = pack2h(v0, v1);
                    }
                }
            } else {
                float* op = outp + (size_t)m * EE;
                #pragma unroll
                for (int nt = 0; nt < 8; nt++) {
                    int col = n0 + wn + nt * 8 + (lane & 3) * 2;
                    op[col]     = acc[mt][nt][half * 2 + 0] + __ldg(bias + col);
                    op[col + 1] = acc[mt][nt][half * 2 + 1] + __ldg(bias + col + 1);
                }
            }
        }
    }
}

// ---------------------------------------------------------------------------
// 2-term fp16 HMMA flash attention (FA2-style) — unchanged from R15-passing.
//   QK: (Qh+Ql)·Kh   PV: (Ph+Pl)·Vh — K and V single fp16.
// ---------------------------------------------------------------------------
#define KVSTG 16384
#define ATT_SMEM (2*KVSTG)
#define NKT (SPAD/64)    // 10

__device__ __forceinline__ void attn_issue(uint32_t sbase, size_t bhq, int j0, int tid)
{
    #pragma unroll
    for (int i = 0; i < 2; i++) {
        int f = tid + 256 * i;          // 512 granules per matrix
        int row = f >> 3, c = f & 7;
        uint32_t doff = swz((uint32_t)(row * 128 + c * 16));
        size_t go = bhq + (size_t)(j0 + row) * DD + c * 8;
        CP16(sbase +         doff, (const char*)(g_Kh + go));
        CP16(sbase + 8192u + doff, (const char*)(g_Vh + go));
    }
}

__global__ __launch_bounds__(256)
void attn_hmma()
{
    extern __shared__ __align__(1024) char smem[];
    const uint32_t sb = smem_u32(smem);
    const int tid = threadIdx.x, lane = tid & 31, wid = tid >> 5;
    const int b = blockIdx.z, h = blockIdx.y, q0 = blockIdx.x * 128;
    const int wm = wid * 16;
    const size_t bh = ((size_t)b * HH + h) * SPAD * DD;

    #pragma unroll
    for (int i = 0; i < 4; i++) {
        int f = tid + 256 * i;          // 1024 granules per matrix
        int row = f >> 3, c = f & 7;
        uint32_t doff = swz((uint32_t)(row * 128 + c * 16));
        size_t go = bh + (size_t)(q0 + row) * DD + c * 8;
        CP16(sb + doff,          (const char*)(g_Qh + go));
        CP16(sb + 16384u + doff, (const char*)(g_Ql + go));
    }
    asm volatile("cp.async.commit_group;" ::: "memory");
    asm volatile("cp.async.wait_group 0;" ::: "memory");
    __syncthreads();

    uint32_t qh[4][4], ql[4][4];
    #pragma unroll
    for (int ks = 0; ks < 4; ks++) {
        uint32_t off = swz((uint32_t)((wm + (lane & 15)) * 128
                                    + (ks * 16 + (lane >> 4) * 8) * 2));
        LDSM4(qh[ks][0], qh[ks][1], qh[ks][2], qh[ks][3], sb + off);
        LDSM4(ql[ks][0], ql[ks][1], ql[ks][2], ql[ks][3], sb + 16384u + off);
    }
    __syncthreads();

    float o[8][4];
    #pragma unroll
    for (int nt = 0; nt < 8; nt++)
        #pragma unroll
        for (int r = 0; r < 4; r++) o[nt][r] = 0.f;
    float m0r = -1e30f, m1r = -1e30f, l0r = 0.f, l1r = 0.f;

    attn_issue(sb, bh, 0, tid);
    asm volatile("cp.async.commit_group;" ::: "memory");
    attn_issue(sb + KVSTG, bh, 64, tid);
    asm volatile("cp.async.commit_group;" ::: "memory");

    for (int t = 0; t < NKT; t++) {
        const uint32_t st = sb + (t & 1) * KVSTG;
        const int j0 = t * 64;
        if (t == NKT - 1) asm volatile("cp.async.wait_group 0;" ::: "memory");
        else              asm volatile("cp.async.wait_group 1;" ::: "memory");
        __syncthreads();

        float s[8][4];
        #pragma unroll
        for (int nt = 0; nt < 8; nt++)
            #pragma unroll
            for (int r = 0; r < 4; r++) s[nt][r] = 0.f;

        #pragma unroll
        for (int ks = 0; ks < 4; ks++) {
            uint32_t kh[8][2];
            #pragma unroll
            for (int p = 0; p < 4; p++) {
                uint32_t off = swz((uint32_t)((p * 16 + (lane & 7) + ((lane >> 4) & 1) * 8) * 128
                                            + (ks * 16 + ((lane >> 3) & 1) * 8) * 2));
                LDSM4(kh[2*p][0], kh[2*p][1], kh[2*p+1][0], kh[2*p+1][1], st + off);
            }
            #pragma unroll
            for (int nt = 0; nt < 8; nt++) MMA16816(s[nt], qh[ks], kh[nt]);
            #pragma unroll
            for (int nt = 0; nt < 8; nt++) MMA16816(s[nt], ql[ks], kh[nt]);
        }

        #pragma unroll
        for (int nt = 0; nt < 8; nt++)
            #pragma unroll
            for (int r = 0; r < 4; r++) s[nt][r] *= 0.125f;
        if (j0 + 64 > SS) {
            #pragma unroll
            for (int nt = 0; nt < 8; nt++) {
                int k0 = j0 + nt * 8 + (lane & 3) * 2;
                if (k0 >= SS)     { s[nt][0] = -1e30f; s[nt][2] = -1e30f; }
                if (k0 + 1 >= SS) { s[nt][1] = -1e30f; s[nt][3] = -1e30f; }
            }
        }

        float mx0 = -1e30f, mx1 = -1e30f;
        #pragma unroll
        for (int nt = 0; nt < 8; nt++) {
            mx0 = fmaxf(mx0, fmaxf(s[nt][0], s[nt][1]));
            mx1 = fmaxf(mx1, fmaxf(s[nt][2], s[nt][3]));
        }
        mx0 = fmaxf(mx0, __shfl_xor_sync(0xffffffffu, mx0, 1));
        mx0 = fmaxf(mx0, __shfl_xor_sync(0xffffffffu, mx0, 2));
        mx1 = fmaxf(mx1, __shfl_xor_sync(0xffffffffu, mx1, 1));
        mx1 = fmaxf(mx1, __shfl_xor_sync(0xffffffffu, mx1, 2));
        float nm0 = fmaxf(m0r, mx0), nm1 = fmaxf(m1r, mx1);
        float c0 = __expf(m0r - nm0), c1 = __expf(m1r - nm1);
        m0r = nm0; m1r = nm1;
        float sum0 = 0.f, sum1 = 0.f;
        #pragma unroll
        for (int nt = 0; nt < 8; nt++) {
            s[nt][0] = __expf(s[nt][0] - nm0); sum0 += s[nt][0];
            s[nt][1] = __expf(s[nt][1] - nm0); sum0 += s[nt][1];
            s[nt][2] = __expf(s[nt][2] - nm1); sum1 += s[nt][2];
            s[nt][3] = __expf(s[nt][3] - nm1); sum1 += s[nt][3];
        }
        sum0 += __shfl_xor_sync(0xffffffffu, sum0, 1);
        sum0 += __shfl_xor_sync(0xffffffffu, sum0, 2);
        sum1 += __shfl_xor_sync(0xffffffffu, sum1, 1);
        sum1 += __shfl_xor_sync(0xffffffffu, sum1, 2);
        l0r = l0r * c0 + sum0;
        l1r = l1r * c1 + sum1;
        #pragma unroll
        for (int nt = 0; nt < 8; nt++) {
            o[nt][0] *= c0; o[nt][1] *= c0;
            o[nt][2] *= c1; o[nt][3] *= c1;
        }

        #pragma unroll
        for (int ks2 = 0; ks2 < 4; ks2++) {
            uint32_t ph[4], pl[4];
            packhl(s[2*ks2][0],   s[2*ks2][1],   ph[0], pl[0]);
            packhl(s[2*ks2][2],   s[2*ks2][3],   ph[1], pl[1]);
            packhl(s[2*ks2+1][0], s[2*ks2+1][1], ph[2], pl[2]);
            packhl(s[2*ks2+1][2], s[2*ks2+1][3], ph[3], pl[3]);

            uint32_t vh[8][2];
            #pragma unroll
            for (int p = 0; p < 4; p++) {
                uint32_t off = swz((uint32_t)((ks2 * 16 + ((lane >> 3) & 1) * 8 + (lane & 7)) * 128
                                            + (p * 16 + ((lane >> 4) & 1) * 8) * 2));
                LDSM4T(vh[2*p][0], vh[2*p][1], vh[2*p+1][0], vh[2*p+1][1], st + 8192u + off);
            }
            #pragma unroll
            for (int nt = 0; nt < 8; nt++) MMA16816(o[nt], ph, vh[nt]);
            #pragma unroll
            for (int nt = 0; nt < 8; nt++) MMA16816(o[nt], pl, vh[nt]);
        }
        __syncthreads();
        if (t + 2 < NKT) {
            attn_issue(st, bh, (t + 2) * 64, tid);
            asm volatile("cp.async.commit_group;" ::: "memory");
        }
    }

    float inv0 = 1.f / l0r, inv1 = 1.f / l1r;
    int qa = q0 + wm + (lane >> 2);
    int qb = qa + 8;
    int cb = h * DD + (lane & 3) * 2;
    if (qa < SS) {
        size_t mrow = ((size_t)b * SS + qa) * EE;
        #pragma unroll
        for (int nt = 0; nt < 8; nt++) {
            uint32_t hv, lv;
            packhl(o[nt][0] * inv0, o[nt][1] * inv0, hv, lv);
            *(uint32_t*)(g_Oh + mrow + cb + nt * 8) = hv;
            *(uint32_t*)(g_Ol + mrow + cb + nt * 8) = lv;
        }
    }
    if (qb < SS) {
        size_t mrow = ((size_t)b * SS + qb) * EE;
        #pragma unroll
        for (int nt = 0; nt < 8; nt++) {
            uint32_t hv, lv;
            packhl(o[nt][2] * inv1, o[nt][3] * inv1, hv, lv);
            *(uint32_t*)(g_Oh + mrow + cb + nt * 8) = hv;
            *(uint32_t*)(g_Ol + mrow + cb + nt * 8) = lv;
        }
    }
}

// ---------------------------------------------------------------------------
extern "C" void kernel_launch(void* const* d_in, const int* in_sizes, int n_in,
                              void* d_out, int out_size)
{
    (void)in_sizes; (void)n_in; (void)out_size;
    const float* x  = (const float*)d_in[0];
    const float* Wq = (const float*)d_in[1];
    const float* Wk = (const float*)d_in[2];
    const float* Wv = (const float*)d_in[3];
    const float* Wo = (const float*)d_in[4];
    const float* bo = (const float*)d_in[5];
    float* out = (float*)d_out;

    __half *pXh, *pXl, *pWh, *pUh, *pOh, *pOl;
    cudaGetSymbolAddress((void**)&pXh, g_Xh);
    cudaGetSymbolAddress((void**)&pXl, g_Xl);
    cudaGetSymbolAddress((void**)&pWh, g_Wh);
    cudaGetSymbolAddress((void**)&pUh, g_Uh);
    cudaGetSymbolAddress((void**)&pOh, g_Oh);
    cudaGetSymbolAddress((void**)&pOl, g_Ol);

    cudaFuncSetAttribute(gemm_hmma, cudaFuncAttributeMaxDynamicSharedMemorySize, GSMEM);
    cudaFuncSetAttribute(attn_hmma, cudaFuncAttributeMaxDynamicSharedMemorySize, ATT_SMEM);

    // 1. converts: x -> fp16 hi/lo; W -> fp16; Wo -> fp16
    split_kernel<<<(unsigned)(((size_t)MPAD * EE) / 1024), 256>>>(
        x, pXh, pXl, (size_t)BSS * EE, (size_t)MPAD * EE);
    convw_kernel<<<dim3(3, HH, EE / 64), 256>>>(Wq, Wk, Wv);
    conv1_kernel<<<(unsigned)(((size_t)EE * EE) / 1024), 256>>>(
        Wo, pUh, (size_t)EE * EE);

    // 2. fused QKV projection -> Qh/Ql (2-term blocks), Kh, Vh (1-term blocks)
    gemm_hmma<<<dim3(MPAD / TM, NQKV / TN), 256, GSMEM>>>(
        pXh, pXl, pWh, nullptr, nullptr, 0);

    // 3. flash attention -> Oh/Ol
    attn_hmma<<<dim3(SPAD / 128, HH, BB), 256, ATT_SMEM>>>();

    // 4. output projection (2-term)
    gemm_hmma<<<dim3(MPAD / TM, EE / TN), 256, GSMEM>>>(
        pOh, pOl, pUh, out, bo, 1);
}

// round 17
// speedup vs baseline: 5.3805x; 1.2382x over previous
#include <cuda_runtime.h>
#include <cuda_fp16.h>
#include <cstdint>

#define BB  32
#define SS  577
#define EE  1024
#define HH  16
#define DD  64
#define BSS (BB*SS)     // 18464
#define MPAD 18560      // 145*128
#define NQKV 3072
#define SPAD 640        // padded seq (5*128)

// ---------------------------------------------------------------------------
// Device global scratch (allocation-free; statically zero-initialized)
// Precision plan: Q,K,V,x,W,Wo,P single fp16; attn-out O hi/lo (feeds proj).
// ---------------------------------------------------------------------------
__device__ __half g_Qh[(size_t)BB*HH*SPAD*DD];
__device__ __half g_Kh[(size_t)BB*HH*SPAD*DD];
__device__ __half g_Vh[(size_t)BB*HH*SPAD*DD];

__device__ __half g_Xh[(size_t)MPAD*EE];
__device__ __half g_Wh[(size_t)NQKV*EE];      // QKV weights, single fp16
__device__ __half g_Uh[(size_t)EE*EE];        // Wo, single fp16
__device__ __half g_Oh[(size_t)MPAD*EE];      // attn out hi (proj A), padding 0
__device__ __half g_Ol[(size_t)MPAD*EE];      // attn out lo

// ---------------------------------------------------------------------------
// Helpers (sm_80-baseline PTX only — harness compiles compute_103, no tcgen05)
// ---------------------------------------------------------------------------
__device__ __forceinline__ uint32_t smem_u32(const void* p) {
    uint32_t a;
    asm("{ .reg .u64 t; cvta.to.shared.u64 t, %1; cvt.u32.u64 %0, t; }"
        : "=r"(a) : "l"(p));
    return a;
}

__device__ __forceinline__ uint32_t swz(uint32_t off) {    // 128B-row swizzle
    return off ^ ((off >> 3) & 0x70);
}

#define CP16(dst, src) \
    asm volatile("cp.async.cg.shared.global [%0], [%1], 16;" \
                 :: "r"(dst), "l"(src) : "memory")

#define LDSM4(r0, r1, r2, r3, addr) \
    asm volatile("ldmatrix.sync.aligned.m8n8.x4.shared.b16 {%0,%1,%2,%3}, [%4];" \
                 : "=r"(r0), "=r"(r1), "=r"(r2), "=r"(r3) : "r"(addr))

#define LDSM4T(r0, r1, r2, r3, addr) \
    asm volatile("ldmatrix.sync.aligned.m8n8.x4.trans.shared.b16 {%0,%1,%2,%3}, [%4];" \
                 : "=r"(r0), "=r"(r1), "=r"(r2), "=r"(r3) : "r"(addr))

#define MMA16816(d, a, b) \
    asm volatile("mma.sync.aligned.m16n8k16.row.col.f32.f16.f16.f32 " \
                 "{%0,%1,%2,%3}, {%4,%5,%6,%7}, {%8,%9}, {%0,%1,%2,%3};" \
                 : "+f"((d)[0]), "+f"((d)[1]), "+f"((d)[2]), "+f"((d)[3]) \
                 : "r"((a)[0]), "r"((a)[1]), "r"((a)[2]), "r"((a)[3]), \
                   "r"((b)[0]), "r"((b)[1]))

// pack two floats into fp16x2 hi + fp16x2 lo (lo = residual)
__device__ __forceinline__ void packhl(float a, float b, uint32_t& hi, uint32_t& lo) {
    __half ha = __float2half_rn(a), hb = __float2half_rn(b);
    __half la = __float2half_rn(a - __half2float(ha));
    __half lb = __float2half_rn(b - __half2float(hb));
    __half2 H = __halves2half2(ha, hb);
    __half2 L = __halves2half2(la, lb);
    hi = *(uint32_t*)&H;
    lo = *(uint32_t*)&L;
}
__device__ __forceinline__ uint32_t pack2h(float a, float b) {
    __half2 H = __halves2half2(__float2half_rn(a), __float2half_rn(b));
    return *(uint32_t*)&H;
}

// ---------------------------------------------------------------------------
// fp32 -> single fp16, zero pad beyond n_valid   [x]
// ---------------------------------------------------------------------------
__global__ void conv1pad_kernel(const float* __restrict__ src,
                                __half* __restrict__ dst,
                                size_t n_valid, size_t n_total)
{
    size_t i = ((size_t)blockIdx.x * 256 + threadIdx.x) * 4;
    if (i >= n_total) return;
    float4 v = make_float4(0.f, 0.f, 0.f, 0.f);
    if (i < n_valid) v = *(const float4*)(src + i);
    ((uint32_t*)dst)[(i >> 1) + 0] = pack2h(v.x, v.y);
    ((uint32_t*)dst)[(i >> 1) + 1] = pack2h(v.z, v.w);
}

// fp32 -> single fp16    [Wo]
__global__ void conv1_kernel(const float* __restrict__ src, __half* __restrict__ dst,
                             size_t n)
{
    size_t i = ((size_t)blockIdx.x * 256 + threadIdx.x) * 4;
    if (i >= n) return;
    float4 v = *(const float4*)(src + i);
    ((uint32_t*)dst)[(i >> 1) + 0] = pack2h(v.x, v.y);
    ((uint32_t*)dst)[(i >> 1) + 1] = pack2h(v.z, v.w);
}

// QKV weights [H][E][D] x3 -> B rows n = mat*1024 + h*64 + d, cols k = e
__global__ void convw_kernel(const float* __restrict__ Wq,
                             const float* __restrict__ Wk,
                             const float* __restrict__ Wv)
{
    __shared__ float t[64][65];
    const int mat = blockIdx.x, h = blockIdx.y, e0 = blockIdx.z * 64;
    const float* W = (mat == 0) ? Wq : (mat == 1) ? Wk : Wv;
    const int tid = threadIdx.x;

    for (int i = tid; i < 64 * 64; i += 256) {
        int e = i >> 6, d = i & 63;
        t[d][e] = W[((size_t)h * EE + e0 + e) * DD + d];
    }
    __syncthreads();

    for (int i = tid; i < 64 * 64; i += 256) {
        int d = i >> 6, e = i & 63;
        size_t off = (size_t)(mat * 1024 + h * 64 + d) * EE + e0 + e;
        g_Wh[off] = __float2half_rn(t[d][e]);
    }
}

// ---------------------------------------------------------------------------
// fp16 HMMA GEMM:  C[M,N] = (Ah[+Al])[M,K] * Bh[N,K]^T
//   mode 0 (QKV): 1-term (Al unused) — outputs rounded to fp16 anyway.
//   mode 1 (proj): 2-term (O hi/lo), fp32 out + bias.
//   KC=64 chunks (128B rows, swz), 16 chunks -> HALF the barriers of KC=32.
//   Stage = Ah,Al,Bh = 48KB; double-buffered 96KB; 2 CTAs/SM (192KB <= 228KB).
// ---------------------------------------------------------------------------
#define TM 128
#define TN 128
#define KC 64
#define TILEB 16384                    // 128 rows x 64 fp16 = 128B rows
#define STAGEB (3*TILEB)               // Ah, Al, Bh = 48KB
#define GSMEM (2*STAGEB)               // 96KB

__device__ __forceinline__ void issue_stage(
    uint32_t sbase,
    const __half* __restrict__ Ah_, const __half* __restrict__ Al_,
    const __half* __restrict__ Bh_,
    int m0, int n0, int kt, int tid, int twoTerm)
{
    #pragma unroll
    for (int i = 0; i < 4; i++) {
        int f = tid + 256 * i;          // 1024 granules per matrix
        int row = f >> 3, c = f & 7;
        uint32_t doff = swz((uint32_t)(row * 128 + c * 16));
        size_t aoff = (size_t)(m0 + row) * EE + kt * KC + c * 8;
        size_t boff = (size_t)(n0 + row) * EE + kt * KC + c * 8;
        CP16(sbase + doff,              (const char*)(Ah_ + aoff));
        if (twoTerm)
            CP16(sbase + TILEB + doff,  (const char*)(Al_ + aoff));
        CP16(sbase + 2 * TILEB + doff,  (const char*)(Bh_ + boff));
    }
}

__device__ __forceinline__ void compute_chunk(
    uint32_t sbase, int wm, int wn, int lane, float (&acc)[2][8][4], int twoTerm)
{
    const uint32_t aH = sbase, aL = sbase + TILEB;
    const uint32_t bH = sbase + 2 * TILEB;
    #pragma unroll
    for (int ks = 0; ks < 4; ks++) {
        uint32_t ah[2][4], al[2][4];
        #pragma unroll
        for (int mt = 0; mt < 2; mt++) {
            uint32_t off = swz((uint32_t)((wm + mt * 16 + (lane & 15)) * 128
                                        + (ks * 16 + (lane >> 4) * 8) * 2));
            LDSM4(ah[mt][0], ah[mt][1], ah[mt][2], ah[mt][3], aH + off);
            if (twoTerm)
                LDSM4(al[mt][0], al[mt][1], al[mt][2], al[mt][3], aL + off);
        }
        #pragma unroll
        for (int p = 0; p < 4; p++) {
            uint32_t bh[4];
            uint32_t off = swz((uint32_t)((wn + p * 16 + (lane & 7) + ((lane >> 4) & 1) * 8) * 128
                                        + (ks * 16 + ((lane >> 3) & 1) * 8) * 2));
            LDSM4(bh[0], bh[1], bh[2], bh[3], bH + off);
            // term-major, same-acc reuse distance 4
            MMA16816(acc[0][2*p],   ah[0], bh);
            MMA16816(acc[1][2*p],   ah[1], bh);
            MMA16816(acc[0][2*p+1], ah[0], bh + 2);
            MMA16816(acc[1][2*p+1], ah[1], bh + 2);
            if (twoTerm) {
                MMA16816(acc[0][2*p],   al[0], bh);
                MMA16816(acc[1][2*p],   al[1], bh);
                MMA16816(acc[0][2*p+1], al[0], bh + 2);
                MMA16816(acc[1][2*p+1], al[1], bh + 2);
            }
        }
    }
}

__global__ __launch_bounds__(256, 2)
void gemm_hmma(const __half* __restrict__ Ah, const __half* __restrict__ Al,
               const __half* __restrict__ Bh,
               float* __restrict__ outp, const float* __restrict__ bias, int mode)
{
    extern __shared__ __align__(1024) char smem[];
    const uint32_t sb = smem_u32(smem);
    const int tid = threadIdx.x, lane = tid & 31, wid = tid >> 5;
    const int m0 = blockIdx.x * TM, n0 = blockIdx.y * TN;
    const int wm = (wid & 3) * 32, wn = (wid >> 2) * 64;
    const int twoTerm = (mode == 1);

    float acc[2][8][4];
    #pragma unroll
    for (int mt = 0; mt < 2; mt++)
        #pragma unroll
        for (int nt = 0; nt < 8; nt++)
            #pragma unroll
            for (int r = 0; r < 4; r++) acc[mt][nt][r] = 0.f;

    const int NK = EE / KC;   // 16
    issue_stage(sb, Ah, Al, Bh, m0, n0, 0, tid, twoTerm);
    asm volatile("cp.async.commit_group;" ::: "memory");

    int buf = 0;
    for (int kt = 0; kt < NK; kt++) {
        if (kt + 1 < NK) {
            issue_stage(sb + (buf ^ 1) * STAGEB, Ah, Al, Bh, m0, n0, kt + 1, tid, twoTerm);
            asm volatile("cp.async.commit_group;" ::: "memory");
            asm volatile("cp.async.wait_group 1;" ::: "memory");
        } else {
            asm volatile("cp.async.wait_group 0;" ::: "memory");
        }
        __syncthreads();
        compute_chunk(sb + buf * STAGEB, wm, wn, lane, acc, twoTerm);
        __syncthreads();
        buf ^= 1;
    }

    #pragma unroll
    for (int mt = 0; mt < 2; mt++) {
        #pragma unroll
        for (int half = 0; half < 2; half++) {
            int m = m0 + wm + mt * 16 + (lane >> 2) + half * 8;
            if (m >= BSS) continue;
            if (mode == 0) {
                int bb = m / SS, ss = m - bb * SS;
                #pragma unroll
                for (int nt = 0; nt < 8; nt++) {
                    int col = n0 + wn + nt * 8 + (lane & 3) * 2;
                    int mat = col >> 10, hh = (col >> 6) & 15, dd = col & 63;
                    size_t off = (((size_t)bb * HH + hh) * SPAD + ss) * DD + dd;
                    __half* dst = (mat == 0 ? g_Qh : (mat == 1 ? g_Kh : g_Vh));
                    *(uint32_t*)(dst + off) =
                        pack2h(acc[mt][nt][half * 2 + 0], acc[mt][nt][half * 2 + 1]);
                }
            } else {
                float* op = outp + (size_t)m * EE;
                #pragma unroll
                for (int nt = 0; nt < 8; nt++) {
                    int col = n0 + wn + nt * 8 + (lane & 3) * 2;
                    op[col]     = acc[mt][nt][half * 2 + 0] + __ldg(bias + col);
                    op[col + 1] = acc[mt][nt][half * 2 + 1] + __ldg(bias + col + 1);
                }
            }
        }
    }
}

// ---------------------------------------------------------------------------
// 1-term fp16 HMMA flash attention (FA2-style).
//   QK: Qh·Kh   PV: Ph·Vh — all single fp16 (output O kept hi/lo for proj).
//   KV stage = Kh(8K)+Vh(8K) = 16KB double-buffered; 2 CTAs/SM.
// ---------------------------------------------------------------------------
#define KVSTG 16384
#define ATT_SMEM (2*KVSTG)
#define NKT (SPAD/64)    // 10

__device__ __forceinline__ void attn_issue(uint32_t sbase, size_t bhq, int j0, int tid)
{
    #pragma unroll
    for (int i = 0; i < 2; i++) {
        int f = tid + 256 * i;          // 512 granules per matrix
        int row = f >> 3, c = f & 7;
        uint32_t doff = swz((uint32_t)(row * 128 + c * 16));
        size_t go = bhq + (size_t)(j0 + row) * DD + c * 8;
        CP16(sbase +         doff, (const char*)(g_Kh + go));
        CP16(sbase + 8192u + doff, (const char*)(g_Vh + go));
    }
}

__global__ __launch_bounds__(256, 2)
void attn_hmma()
{
    extern __shared__ __align__(1024) char smem[];
    const uint32_t sb = smem_u32(smem);
    const int tid = threadIdx.x, lane = tid & 31, wid = tid >> 5;
    const int b = blockIdx.z, h = blockIdx.y, q0 = blockIdx.x * 128;
    const int wm = wid * 16;
    const size_t bh = ((size_t)b * HH + h) * SPAD * DD;

    // stage Q (16KB) through stage0 region, build frags, release
    #pragma unroll
    for (int i = 0; i < 4; i++) {
        int f = tid + 256 * i;          // 1024 granules
        int row = f >> 3, c = f & 7;
        uint32_t doff = swz((uint32_t)(row * 128 + c * 16));
        CP16(sb + doff, (const char*)(g_Qh + bh + (size_t)(q0 + row) * DD + c * 8));
    }
    asm volatile("cp.async.commit_group;" ::: "memory");
    asm volatile("cp.async.wait_group 0;" ::: "memory");
    __syncthreads();

    uint32_t qh[4][4];
    #pragma unroll
    for (int ks = 0; ks < 4; ks++) {
        uint32_t off = swz((uint32_t)((wm + (lane & 15)) * 128
                                    + (ks * 16 + (lane >> 4) * 8) * 2));
        LDSM4(qh[ks][0], qh[ks][1], qh[ks][2], qh[ks][3], sb + off);
    }
    __syncthreads();

    float o[8][4];
    #pragma unroll
    for (int nt = 0; nt < 8; nt++)
        #pragma unroll
        for (int r = 0; r < 4; r++) o[nt][r] = 0.f;
    float m0r = -1e30f, m1r = -1e30f, l0r = 0.f, l1r = 0.f;

    attn_issue(sb, bh, 0, tid);
    asm volatile("cp.async.commit_group;" ::: "memory");
    attn_issue(sb + KVSTG, bh, 64, tid);
    asm volatile("cp.async.commit_group;" ::: "memory");

    for (int t = 0; t < NKT; t++) {
        const uint32_t st = sb + (t & 1) * KVSTG;
        const int j0 = t * 64;
        if (t == NKT - 1) asm volatile("cp.async.wait_group 0;" ::: "memory");
        else              asm volatile("cp.async.wait_group 1;" ::: "memory");
        __syncthreads();

        float s[8][4];
        #pragma unroll
        for (int nt = 0; nt < 8; nt++)
            #pragma unroll
            for (int r = 0; r < 4; r++) s[nt][r] = 0.f;

        #pragma unroll
        for (int ks = 0; ks < 4; ks++) {
            uint32_t kh[8][2];
            #pragma unroll
            for (int p = 0; p < 4; p++) {
                uint32_t off = swz((uint32_t)((p * 16 + (lane & 7) + ((lane >> 4) & 1) * 8) * 128
                                            + (ks * 16 + ((lane >> 3) & 1) * 8) * 2));
                LDSM4(kh[2*p][0], kh[2*p][1], kh[2*p+1][0], kh[2*p+1][1], st + off);
            }
            #pragma unroll
            for (int nt = 0; nt < 8; nt++) MMA16816(s[nt], qh[ks], kh[nt]);
        }

        #pragma unroll
        for (int nt = 0; nt < 8; nt++)
            #pragma unroll
            for (int r = 0; r < 4; r++) s[nt][r] *= 0.125f;
        if (j0 + 64 > SS) {
            #pragma unroll
            for (int nt = 0; nt < 8; nt++) {
                int k0 = j0 + nt * 8 + (lane & 3) * 2;
                if (k0 >= SS)     { s[nt][0] = -1e30f; s[nt][2] = -1e30f; }
                if (k0 + 1 >= SS) { s[nt][1] = -1e30f; s[nt][3] = -1e30f; }
            }
        }

        float mx0 = -1e30f, mx1 = -1e30f;
        #pragma unroll
        for (int nt = 0; nt < 8; nt++) {
            mx0 = fmaxf(mx0, fmaxf(s[nt][0], s[nt][1]));
            mx1 = fmaxf(mx1, fmaxf(s[nt][2], s[nt][3]));
        }
        mx0 = fmaxf(mx0, __shfl_xor_sync(0xffffffffu, mx0, 1));
        mx0 = fmaxf(mx0, __shfl_xor_sync(0xffffffffu, mx0, 2));
        mx1 = fmaxf(mx1, __shfl_xor_sync(0xffffffffu, mx1, 1));
        mx1 = fmaxf(mx1, __shfl_xor_sync(0xffffffffu, mx1, 2));
        float nm0 = fmaxf(m0r, mx0), nm1 = fmaxf(m1r, mx1);
        float c0 = __expf(m0r - nm0), c1 = __expf(m1r - nm1);
        m0r = nm0; m1r = nm1;
        float sum0 = 0.f, sum1 = 0.f;
        #pragma unroll
        for (int nt = 0; nt < 8; nt++) {
            s[nt][0] = __expf(s[nt][0] - nm0); sum0 += s[nt][0];
            s[nt][1] = __expf(s[nt][1] - nm0); sum0 += s[nt][1];
            s[nt][2] = __expf(s[nt][2] - nm1); sum1 += s[nt][2];
            s[nt][3] = __expf(s[nt][3] - nm1); sum1 += s[nt][3];
        }
        sum0 += __shfl_xor_sync(0xffffffffu, sum0, 1);
        sum0 += __shfl_xor_sync(0xffffffffu, sum0, 2);
        sum1 += __shfl_xor_sync(0xffffffffu, sum1, 1);
        sum1 += __shfl_xor_sync(0xffffffffu, sum1, 2);
        l0r = l0r * c0 + sum0;
        l1r = l1r * c1 + sum1;
        #pragma unroll
        for (int nt = 0; nt < 8; nt++) {
            o[nt][0] *= c0; o[nt][1] *= c0;
            o[nt][2] *= c1; o[nt][3] *= c1;
        }

        #pragma unroll
        for (int ks2 = 0; ks2 < 4; ks2++) {
            uint32_t ph[4];
            ph[0] = pack2h(s[2*ks2][0],   s[2*ks2][1]);
            ph[1] = pack2h(s[2*ks2][2],   s[2*ks2][3]);
            ph[2] = pack2h(s[2*ks2+1][0], s[2*ks2+1][1]);
            ph[3] = pack2h(s[2*ks2+1][2], s[2*ks2+1][3]);

            uint32_t vh[8][2];
            #pragma unroll
            for (int p = 0; p < 4; p++) {
                uint32_t off = swz((uint32_t)((ks2 * 16 + ((lane >> 3) & 1) * 8 + (lane & 7)) * 128
                                            + (p * 16 + ((lane >> 4) & 1) * 8) * 2));
                LDSM4T(vh[2*p][0], vh[2*p][1], vh[2*p+1][0], vh[2*p+1][1], st + 8192u + off);
            }
            #pragma unroll
            for (int nt = 0; nt < 8; nt++) MMA16816(o[nt], ph, vh[nt]);
        }
        __syncthreads();
        if (t + 2 < NKT) {
            attn_issue(st, bh, (t + 2) * 64, tid);
            asm volatile("cp.async.commit_group;" ::: "memory");
        }
    }

    // epilogue: O/l -> fp16 hi/lo in proj-A layout [b*SS+s][h*64+d]
    float inv0 = 1.f / l0r, inv1 = 1.f / l1r;
    int qa = q0 + wm + (lane >> 2);
    int qb = qa + 8;
    int cb = h * DD + (lane & 3) * 2;
    if (qa < SS) {
        size_t mrow = ((size_t)b * SS + qa) * EE;
        #pragma unroll
        for (int nt = 0; nt < 8; nt++) {
            uint32_t hv, lv;
            packhl(o[nt][0] * inv0, o[nt][1] * inv0, hv, lv);
            *(uint32_t*)(g_Oh + mrow + cb + nt * 8) = hv;
            *(uint32_t*)(g_Ol + mrow + cb + nt * 8) = lv;
        }
    }
    if (qb < SS) {
        size_t mrow = ((size_t)b * SS + qb) * EE;
        #pragma unroll
        for (int nt = 0; nt < 8; nt++) {
            uint32_t hv, lv;
            packhl(o[nt][2] * inv1, o[nt][3] * inv1, hv, lv);
            *(uint32_t*)(g_Oh + mrow + cb + nt * 8) = hv;
            *(uint32_t*)(g_Ol + mrow + cb + nt * 8) = lv;
        }
    }
}

// ---------------------------------------------------------------------------
extern "C" void kernel_launch(void* const* d_in, const int* in_sizes, int n_in,
                              void* d_out, int out_size)
{
    (void)in_sizes; (void)n_in; (void)out_size;
    const float* x  = (const float*)d_in[0];
    const float* Wq = (const float*)d_in[1];
    const float* Wk = (const float*)d_in[2];
    const float* Wv = (const float*)d_in[3];
    const float* Wo = (const float*)d_in[4];
    const float* bo = (const float*)d_in[5];
    float* out = (float*)d_out;

    __half *pXh, *pWh, *pUh, *pOh, *pOl;
    cudaGetSymbolAddress((void**)&pXh, g_Xh);
    cudaGetSymbolAddress((void**)&pWh, g_Wh);
    cudaGetSymbolAddress((void**)&pUh, g_Uh);
    cudaGetSymbolAddress((void**)&pOh, g_Oh);
    cudaGetSymbolAddress((void**)&pOl, g_Ol);

    cudaFuncSetAttribute(gemm_hmma, cudaFuncAttributeMaxDynamicSharedMemorySize, GSMEM);
    cudaFuncSetAttribute(attn_hmma, cudaFuncAttributeMaxDynamicSharedMemorySize, ATT_SMEM);

    // 1. converts: x -> fp16 (padded); W -> fp16; Wo -> fp16
    conv1pad_kernel<<<(unsigned)(((size_t)MPAD * EE) / 1024), 256>>>(
        x, pXh, (size_t)BSS * EE, (size_t)MPAD * EE);
    convw_kernel<<<dim3(3, HH, EE / 64), 256>>>(Wq, Wk, Wv);
    conv1_kernel<<<(unsigned)(((size_t)EE * EE) / 1024), 256>>>(
        Wo, pUh, (size_t)EE * EE);

    // 2. fused QKV projection (1-term) -> Qh, Kh, Vh
    gemm_hmma<<<dim3(MPAD / TM, NQKV / TN), 256, GSMEM>>>(
        pXh, nullptr, pWh, nullptr, nullptr, 0);

    // 3. flash attention (1-term) -> Oh/Ol
    attn_hmma<<<dim3(SPAD / 128, HH, BB), 256, ATT_SMEM>>>();

    // 4. output projection (2-term: O hi/lo)
    gemm_hmma<<<dim3(MPAD / TM, EE / TN), 256, GSMEM>>>(
        pOh, pOl, pUh, out, bo, 1);
}